// round 1
// baseline (speedup 1.0000x reference)
#include <cuda_runtime.h>
#include <math.h>
#include <stdint.h>

// Problem dims
#define BATCH 1024
#define NB    512     // buses
#define HD    512     // hidden
#define KP    528     // padded input dim (1 + 512 -> 528, multiple of 16)
#define BNTOT (BATCH*NB)   // 524288

// ---------------------------------------------------------------------------
// Scratch (device globals; no allocation anywhere)
// ---------------------------------------------------------------------------
__device__ float g_X   [BATCH*KP];     // normalized [tn | pn | 0-pad]
__device__ float g_W0p [KP*HD];        // W0 padded with zero rows 513..527
__device__ float g_LbT [NB*NB];        // lambda_b transposed
__device__ float g_U   [3*BATCH*HD];   // pre-activations (3 streams stacked)
__device__ float g_Av  [3*BATCH*HD];   // activations ping
__device__ float g_Bv  [3*BATCH*HD];   // activations pong
__device__ float g_SC  [2*BATCH*NB];   // [sin(out) ; cos(out)]
__device__ float g_SS  [2*BATCH*NB];   // [sin@LbT ; cos@LbT]

// ---------------------------------------------------------------------------
// SGEMM: C[M,N] = A[M,K] @ B[K,N] (+ bias[col] for rows < bias_rows)
// row-major, M%64==0, N%64==0, K%16==0, everything float4-aligned
// Tile 64x64x16, 128 threads, 8x4 per-thread microtile
// ---------------------------------------------------------------------------
#define TBM 64
#define TBN 64
#define TBK 16
#define APAD 4

__global__ void __launch_bounds__(128) sgemm_kernel(
    const float* __restrict__ A, const float* __restrict__ B,
    float* __restrict__ C, int M, int N, int K,
    const float* __restrict__ bias, int bias_rows)
{
    __shared__ float As[TBK][TBM + APAD];
    __shared__ float Bs[TBK][TBN];

    const int tid = threadIdx.x;
    const int tx  = tid & 15;    // N direction (16 * 4 = 64)
    const int ty  = tid >> 4;    // M direction (8 * 8 = 64)
    const int m0  = blockIdx.y * TBM;
    const int n0  = blockIdx.x * TBN;

    float acc[8][4];
#pragma unroll
    for (int i = 0; i < 8; i++)
#pragma unroll
        for (int j = 0; j < 4; j++) acc[i][j] = 0.f;

    const int aRow0 = tid >> 2;        // 0..31
    const int aK    = (tid & 3) * 4;   // 0,4,8,12
    const int bRow0 = tid >> 4;        // 0..7
    const int bN    = (tid & 15) * 4;  // 0..60

    for (int k0 = 0; k0 < K; k0 += TBK) {
        // A tile -> shared (transposed)
#pragma unroll
        for (int r = 0; r < 2; r++) {
            int row = aRow0 + r * 32;
            float4 v = *reinterpret_cast<const float4*>(
                &A[(size_t)(m0 + row) * K + k0 + aK]);
            As[aK + 0][row] = v.x;
            As[aK + 1][row] = v.y;
            As[aK + 2][row] = v.z;
            As[aK + 3][row] = v.w;
        }
        // B tile -> shared
#pragma unroll
        for (int r = 0; r < 2; r++) {
            int row = bRow0 + r * 8;
            *reinterpret_cast<float4*>(&Bs[row][bN]) =
                *reinterpret_cast<const float4*>(
                    &B[(size_t)(k0 + row) * N + n0 + bN]);
        }
        __syncthreads();

#pragma unroll
        for (int k = 0; k < TBK; k++) {
            float a[8], b[4];
            *reinterpret_cast<float4*>(a)     = *reinterpret_cast<const float4*>(&As[k][ty * 8]);
            *reinterpret_cast<float4*>(a + 4) = *reinterpret_cast<const float4*>(&As[k][ty * 8 + 4]);
            *reinterpret_cast<float4*>(b)     = *reinterpret_cast<const float4*>(&Bs[k][tx * 4]);
#pragma unroll
            for (int i = 0; i < 8; i++)
#pragma unroll
                for (int j = 0; j < 4; j++)
                    acc[i][j] += a[i] * b[j];
        }
        __syncthreads();
    }

    float4 bv = make_float4(0.f, 0.f, 0.f, 0.f);
    if (bias) bv = *reinterpret_cast<const float4*>(&bias[n0 + tx * 4]);

#pragma unroll
    for (int i = 0; i < 8; i++) {
        int row = m0 + ty * 8 + i;
        float4 o;
        o.x = acc[i][0]; o.y = acc[i][1]; o.z = acc[i][2]; o.w = acc[i][3];
        if (bias && row < bias_rows) {
            o.x += bv.x; o.y += bv.y; o.z += bv.z; o.w += bv.w;
        }
        *reinterpret_cast<float4*>(&C[(size_t)row * N + n0 + tx * 4]) = o;
    }
}

// ---------------------------------------------------------------------------
// Elementwise kernels
// ---------------------------------------------------------------------------
__global__ void build_x_kernel(const float* __restrict__ t,
                               const float* __restrict__ p,
                               const float* __restrict__ pl,
                               const float* __restrict__ pu)
{
    int idx = blockIdx.x * blockDim.x + threadIdx.x;
    if (idx >= BATCH * KP) return;
    int row = idx / KP;
    int col = idx - row * KP;
    float v;
    if (col == 0) {
        v = 0.2f * t[row] - 1.0f;               // 2*t/T_MAX - 1
    } else if (col <= NB) {
        int j = col - 1;
        float lo = pl[j], hi = pu[j];
        v = (hi == lo) ? 0.f : (2.f * (p[row * NB + j] - lo) / (hi - lo) - 1.f);
    } else {
        v = 0.f;
    }
    g_X[idx] = v;
}

__global__ void pad_w0_kernel(const float* __restrict__ W0)
{
    int idx = blockIdx.x * blockDim.x + threadIdx.x;
    if (idx >= KP * HD) return;
    int row = idx / HD;
    g_W0p[idx] = (row < NB + 1) ? W0[idx] : 0.f;   // same ld (512) both sides
}

__global__ void transpose_lb_kernel(const float* __restrict__ lb)
{
    int idx = blockIdx.x * blockDim.x + threadIdx.x;
    if (idx >= NB * NB) return;
    int i = idx / NB;
    int j = idx - i * NB;
    g_LbT[j * NB + i] = lb[idx];
}

// layer 0 activation: u-dot is the constant row 0.2*W0[0,:], u-ddot = 0
__global__ void act0_kernel(const float* __restrict__ W0)
{
    int idx = blockIdx.x * blockDim.x + threadIdx.x;
    if (idx >= BNTOT) return;
    int col = idx & (HD - 1);
    float u   = g_U[idx];
    float a   = tanhf(u);
    float s   = 1.f - a * a;
    float gth = 0.2f * W0[col];      // W0 row 0
    g_Av[idx]             = a;
    g_Av[BNTOT + idx]     = s * gth;
    g_Av[2 * BNTOT + idx] = -2.f * a * s * gth * gth;
}

// layers 1,2 activation: propagate (value, d1, d2) through tanh
__global__ void act12_kernel(const float* __restrict__ U, float* __restrict__ Aout)
{
    int idx = blockIdx.x * blockDim.x + threadIdx.x;
    if (idx >= BNTOT) return;
    float u = U[idx];
    float v = U[BNTOT + idx];
    float w = U[2 * BNTOT + idx];
    float a = tanhf(u);
    float s = 1.f - a * a;
    Aout[idx]             = a;
    Aout[BNTOT + idx]     = s * v;
    Aout[2 * BNTOT + idx] = s * (w - 2.f * a * v * v);
}

__global__ void sincos_kernel(const float* __restrict__ out)
{
    int idx = blockIdx.x * blockDim.x + threadIdx.x;
    if (idx >= BNTOT) return;
    float s, c;
    sincosf(out[idx], &s, &c);
    g_SC[idx]         = s;
    g_SC[BNTOT + idx] = c;
}

// physics = lm*out_tt + ld*out_t + sin_i*(cos@LbT) - cos_i*(sin@LbT) - p
// out_tt currently sits in the physics slot of d_out; overwrite in place.
__global__ void final_kernel(float* __restrict__ out,
                             const float* __restrict__ lm,
                             const float* __restrict__ ld,
                             const float* __restrict__ p)
{
    int idx = blockIdx.x * blockDim.x + threadIdx.x;
    if (idx >= BNTOT) return;
    int col = idx & (NB - 1);
    float ot  = out[BNTOT + idx];
    float ott = out[2 * BNTOT + idx];
    float s   = g_SC[idx];
    float c   = g_SC[BNTOT + idx];
    float conn = s * g_SS[BNTOT + idx] - c * g_SS[idx];
    out[2 * BNTOT + idx] = lm[col] * ott + ld[col] * ot + conn - p[idx];
}

// ---------------------------------------------------------------------------
// Launch
// ---------------------------------------------------------------------------
extern "C" void kernel_launch(void* const* d_in, const int* in_sizes, int n_in,
                              void* d_out, int out_size)
{
    const float* t    = (const float*)d_in[0];
    const float* p    = (const float*)d_in[1];
    const float* W0   = (const float*)d_in[2];
    const float* b0   = (const float*)d_in[3];
    const float* W1   = (const float*)d_in[4];
    const float* b1   = (const float*)d_in[5];
    const float* W2   = (const float*)d_in[6];
    const float* b2   = (const float*)d_in[7];
    const float* Wout = (const float*)d_in[8];
    const float* bout = (const float*)d_in[9];
    const float* lm   = (const float*)d_in[10];
    const float* ld   = (const float*)d_in[11];
    const float* lb   = (const float*)d_in[12];
    const float* pl   = (const float*)d_in[13];
    const float* pu   = (const float*)d_in[14];
    float* out = (float*)d_out;

    float *pX, *pW0p, *pLbT, *pU, *pA, *pB, *pSC, *pSS;
    cudaGetSymbolAddress((void**)&pX,   g_X);
    cudaGetSymbolAddress((void**)&pW0p, g_W0p);
    cudaGetSymbolAddress((void**)&pLbT, g_LbT);
    cudaGetSymbolAddress((void**)&pU,   g_U);
    cudaGetSymbolAddress((void**)&pA,   g_Av);
    cudaGetSymbolAddress((void**)&pB,   g_Bv);
    cudaGetSymbolAddress((void**)&pSC,  g_SC);
    cudaGetSymbolAddress((void**)&pSS,  g_SS);

    const int EW = 256;
    // prep
    build_x_kernel     <<<(BATCH * KP + EW - 1) / EW, EW>>>(t, p, pl, pu);
    pad_w0_kernel      <<<(KP * HD + EW - 1) / EW, EW>>>(W0);
    transpose_lb_kernel<<<(NB * NB + EW - 1) / EW, EW>>>(lb);

    dim3 blk(128);
    // layer 0: [1024,528] @ [528,512] + b0
    sgemm_kernel<<<dim3(HD / TBN, BATCH / TBM), blk>>>(pX, pW0p, pU, BATCH, HD, KP, b0, BATCH);
    act0_kernel<<<(BNTOT + EW - 1) / EW, EW>>>(W0);

    // layer 1: [3072,512] @ [512,512] (+b1 on value stream)
    sgemm_kernel<<<dim3(HD / TBN, 3 * BATCH / TBM), blk>>>(pA, W1, pU, 3 * BATCH, HD, HD, b1, BATCH);
    act12_kernel<<<(BNTOT + EW - 1) / EW, EW>>>(pU, pB);

    // layer 2
    sgemm_kernel<<<dim3(HD / TBN, 3 * BATCH / TBM), blk>>>(pB, W2, pU, 3 * BATCH, HD, HD, b2, BATCH);
    act12_kernel<<<(BNTOT + EW - 1) / EW, EW>>>(pU, pA);

    // output layer: writes [out | out_t | out_tt] directly into d_out
    sgemm_kernel<<<dim3(NB / TBN, 3 * BATCH / TBM), blk>>>(pA, Wout, out, 3 * BATCH, NB, HD, bout, BATCH);

    // connectivity: [sin;cos] @ LbT
    sincos_kernel<<<(BNTOT + EW - 1) / EW, EW>>>(out);
    sgemm_kernel<<<dim3(NB / TBN, 2 * BATCH / TBM), blk>>>(pSC, pLbT, pSS, 2 * BATCH, NB, NB, nullptr, 0);

    // physics residual (overwrites out_tt slot)
    final_kernel<<<(BNTOT + EW - 1) / EW, EW>>>(out, lm, ld, p);
}

// round 3
// speedup vs baseline: 1.1878x; 1.1878x over previous
#include <cuda_runtime.h>
#include <cuda_bf16.h>
#include <math.h>
#include <stdint.h>

// Problem dims
#define BATCH 1024
#define NB    512
#define HD    512
#define KP    576            // padded input dim (1+512 -> 576 = 18*32)
#define BNTOT (BATCH*NB)     // 524288

// ---------------------------------------------------------------------------
// Scratch (device globals)
// ---------------------------------------------------------------------------
__device__ __nv_bfloat16 g_Xh[BATCH*KP],  g_Xl[BATCH*KP];
__device__ __nv_bfloat16 g_W0Th[HD*KP],   g_W0Tl[HD*KP];     // W0^T padded [512 x 576]
__device__ __nv_bfloat16 g_W1Th[HD*HD],   g_W1Tl[HD*HD];
__device__ __nv_bfloat16 g_W2Th[HD*HD],   g_W2Tl[HD*HD];
__device__ __nv_bfloat16 g_WoTh[HD*NB],   g_WoTl[HD*NB];     // Wout^T [512 x 512]
__device__ __nv_bfloat16 g_Lbh[NB*NB],    g_Lbl[NB*NB];      // lambda_b [i][j] (acts as B^T)
__device__ __nv_bfloat16 g_Ah[3*BNTOT],   g_Al[3*BNTOT];     // activations ping
__device__ __nv_bfloat16 g_Bh[3*BNTOT],   g_Bl[3*BNTOT];     // activations pong
__device__ __nv_bfloat16 g_SCh[2*BNTOT],  g_SCl[2*BNTOT];    // [sin ; cos]
__device__ float g_U [3*BNTOT];                              // pre-activations fp32
__device__ float g_SS[2*BNTOT];                              // [sin@LbT ; cos@LbT]

__device__ __forceinline__ void split2(float x, __nv_bfloat16* h, __nv_bfloat16* l) {
    __nv_bfloat16 hi = __float2bfloat16_rn(x);
    *h = hi;
    *l = __float2bfloat16_rn(x - __bfloat162float(hi));
}

__device__ __forceinline__ uint32_t smem_u32(const void* p) {
    uint32_t a;
    asm("{ .reg .u64 t; cvta.to.shared.u64 t, %1; cvt.u32.u64 %0, t; }" : "=r"(a) : "l"(p));
    return a;
}

__device__ __forceinline__ void mma_bf16(float* d, const uint32_t* a, uint32_t b0, uint32_t b1) {
    asm volatile(
        "mma.sync.aligned.m16n8k16.row.col.f32.bf16.bf16.f32 "
        "{%0,%1,%2,%3},{%4,%5,%6,%7},{%8,%9},{%0,%1,%2,%3};"
        : "+f"(d[0]), "+f"(d[1]), "+f"(d[2]), "+f"(d[3])
        : "r"(a[0]), "r"(a[1]), "r"(a[2]), "r"(a[3]), "r"(b0), "r"(b1));
}

// ---------------------------------------------------------------------------
// HMMA split-bf16 GEMM: C[M,N] = A[M,K] * B^T  (B stored [N,K] row-major)
// C = Ah*Bh + Ah*Bl + Al*Bh  via 3 K-segments. CTA tile 128x128, Kc=32.
// 8 warps: warp (wm=wid&3, wn=wid>>2) owns 32(M) x 64(N).
// smem: 2 stages x (A 8KB + B 8KB), XOR swizzle chunk^((row>>1)&3).
// ---------------------------------------------------------------------------
__global__ void __launch_bounds__(256)
hmma_gemm(const __nv_bfloat16* __restrict__ Ah, const __nv_bfloat16* __restrict__ Al,
          const __nv_bfloat16* __restrict__ Bh, const __nv_bfloat16* __restrict__ Bl,
          float* __restrict__ C, int M, int N, int K,
          const float* __restrict__ bias, int bias_rows)
{
    __shared__ __align__(1024) char smem[32768];
    const uint32_t sb = smem_u32(smem);
    const int tid = threadIdx.x;
    const int lane = tid & 31;
    const int wid = tid >> 5;
    const int wm = wid & 3;          // M direction (4 x 32 = 128)
    const int wn = wid >> 2;         // N direction (2 x 64 = 128)
    const int m0 = blockIdx.y * 128;
    const int n0 = blockIdx.x * 128;
    const int ncK = K >> 5;
    const int TOT = 3 * ncK;

    float acc[2][8][4];
#pragma unroll
    for (int i = 0; i < 2; i++)
#pragma unroll
        for (int j = 0; j < 8; j++)
#pragma unroll
            for (int q = 0; q < 4; q++) acc[i][j][q] = 0.f;

    // per-thread load coords (4 x 16B cp.async per operand per stage)
    const int ldRow = tid >> 2;          // 0..63  (x2 => 128 rows)
    const int ldCh  = tid & 3;           // 16B chunk within 64B row

    auto load_stage = [&](int c, int stg) {
        const int s  = c / ncK;
        const int kk = c - s * ncK;
        const __nv_bfloat16* Ap = (s < 2) ? Ah : Al;
        const __nv_bfloat16* Bp = (s == 1) ? Bl : Bh;
        const int kbase = kk << 5;
        const uint32_t abase = sb + stg * 16384;
        const uint32_t bbase = abase + 8192;
#pragma unroll
        for (int h = 0; h < 2; h++) {
            int row = ldRow + h * 64;
            uint32_t sa = abase + row * 64 + ((ldCh ^ ((row >> 1) & 3)) << 4);
            const void* ga = Ap + (size_t)(m0 + row) * K + kbase + ldCh * 8;
            asm volatile("cp.async.cg.shared.global [%0], [%1], 16;" :: "r"(sa), "l"(ga));
        }
#pragma unroll
        for (int h = 0; h < 2; h++) {
            int row = ldRow + h * 64;
            uint32_t sa = bbase + row * 64 + ((ldCh ^ ((row >> 1) & 3)) << 4);
            const void* ga = Bp + (size_t)(n0 + row) * K + kbase + ldCh * 8;
            asm volatile("cp.async.cg.shared.global [%0], [%1], 16;" :: "r"(sa), "l"(ga));
        }
    };

    load_stage(0, 0);
    asm volatile("cp.async.commit_group;" ::: "memory");

    for (int c = 0; c < TOT; c++) {
        if (c + 1 < TOT) load_stage(c + 1, (c + 1) & 1);
        asm volatile("cp.async.commit_group;" ::: "memory");
        asm volatile("cp.async.wait_group 1;" ::: "memory");
        __syncthreads();

        const uint32_t abase = sb + (c & 1) * 16384;
        const uint32_t bbase = abase + 8192;

#pragma unroll
        for (int kb = 0; kb < 2; kb++) {
            uint32_t a[2][4];
#pragma unroll
            for (int i = 0; i < 2; i++) {
                int row = wm * 32 + i * 16 + (lane & 15);
                int ch  = kb * 2 + (lane >> 4);
                uint32_t ad = abase + row * 64 + ((ch ^ ((row >> 1) & 3)) << 4);
                asm volatile("ldmatrix.sync.aligned.m8n8.x4.shared.b16 {%0,%1,%2,%3}, [%4];"
                             : "=r"(a[i][0]), "=r"(a[i][1]), "=r"(a[i][2]), "=r"(a[i][3])
                             : "r"(ad));
            }
#pragma unroll
            for (int j = 0; j < 4; j++) {
                uint32_t b[4];
                int rn  = (lane & 7) + ((lane >> 4) << 3);
                int row = wn * 64 + j * 16 + rn;
                int ch  = kb * 2 + ((lane >> 3) & 1);
                uint32_t bd = bbase + row * 64 + ((ch ^ ((row >> 1) & 3)) << 4);
                asm volatile("ldmatrix.sync.aligned.m8n8.x4.shared.b16 {%0,%1,%2,%3}, [%4];"
                             : "=r"(b[0]), "=r"(b[1]), "=r"(b[2]), "=r"(b[3])
                             : "r"(bd));
#pragma unroll
                for (int i = 0; i < 2; i++) {
                    mma_bf16(acc[i][2 * j],     a[i], b[0], b[1]);
                    mma_bf16(acc[i][2 * j + 1], a[i], b[2], b[3]);
                }
            }
        }
        __syncthreads();
    }

    // epilogue
    const int gr  = lane >> 2;           // row within 8
    const int cp2 = (lane & 3) * 2;      // col pair
#pragma unroll
    for (int i = 0; i < 2; i++) {
#pragma unroll
        for (int j8 = 0; j8 < 8; j8++) {
            int col = n0 + wn * 64 + j8 * 8 + cp2;
            int r0  = m0 + wm * 32 + i * 16 + gr;
            float bx = 0.f, by = 0.f;
            if (bias) { bx = bias[col]; by = bias[col + 1]; }
#pragma unroll
            for (int rr = 0; rr < 2; rr++) {
                int row = r0 + rr * 8;
                float2 v;
                v.x = acc[i][j8][2 * rr + 0];
                v.y = acc[i][j8][2 * rr + 1];
                if (bias && row < bias_rows) { v.x += bx; v.y += by; }
                *reinterpret_cast<float2*>(&C[(size_t)row * N + col]) = v;
            }
        }
    }
}

// ---------------------------------------------------------------------------
// Elementwise / prep kernels
// ---------------------------------------------------------------------------
__global__ void build_x_kernel(const float* __restrict__ t, const float* __restrict__ p,
                               const float* __restrict__ pl, const float* __restrict__ pu)
{
    int idx = blockIdx.x * blockDim.x + threadIdx.x;
    if (idx >= BATCH * KP) return;
    int row = idx / KP, col = idx - row * KP;
    float v;
    if (col == 0) v = 0.2f * t[row] - 1.0f;
    else if (col <= NB) {
        int j = col - 1;
        float lo = pl[j], hi = pu[j];
        v = (hi == lo) ? 0.f : (2.f * (p[row * NB + j] - lo) / (hi - lo) - 1.f);
    } else v = 0.f;
    split2(v, &g_Xh[idx], &g_Xl[idx]);
}

// out[n*Kout+k] = split( k<Kin ? W[k*Nw+n] : 0 )
__global__ void wsplitT_kernel(const float* __restrict__ W,
                               __nv_bfloat16* __restrict__ oh, __nv_bfloat16* __restrict__ ol,
                               int Kin, int Nw, int Kout)
{
    int idx = blockIdx.x * blockDim.x + threadIdx.x;
    if (idx >= Nw * Kout) return;
    int n = idx / Kout, k = idx - n * Kout;
    float v = (k < Kin) ? W[(size_t)k * Nw + n] : 0.f;
    split2(v, &oh[idx], &ol[idx]);
}

__global__ void lbsplit_kernel(const float* __restrict__ lb)
{
    int idx = blockIdx.x * blockDim.x + threadIdx.x;
    if (idx >= NB * NB) return;
    split2(lb[idx], &g_Lbh[idx], &g_Lbl[idx]);
}

__global__ void act0_kernel(const float* __restrict__ W0)
{
    int idx = blockIdx.x * blockDim.x + threadIdx.x;
    if (idx >= BNTOT) return;
    int col = idx & (HD - 1);
    float u = g_U[idx];
    float a = tanhf(u);
    float ssq = 1.f - a * a;
    float gth = 0.2f * W0[col];      // W0 row 0
    split2(a,                          &g_Ah[idx],             &g_Al[idx]);
    split2(ssq * gth,                  &g_Ah[BNTOT + idx],     &g_Al[BNTOT + idx]);
    split2(-2.f * a * ssq * gth * gth, &g_Ah[2 * BNTOT + idx], &g_Al[2 * BNTOT + idx]);
}

__global__ void act12_kernel(const float* __restrict__ U,
                             __nv_bfloat16* __restrict__ oh, __nv_bfloat16* __restrict__ ol)
{
    int idx = blockIdx.x * blockDim.x + threadIdx.x;
    if (idx >= BNTOT) return;
    float u = U[idx];
    float v = U[BNTOT + idx];
    float w = U[2 * BNTOT + idx];
    float a = tanhf(u);
    float ssq = 1.f - a * a;
    split2(a,                           &oh[idx],             &ol[idx]);
    split2(ssq * v,                     &oh[BNTOT + idx],     &ol[BNTOT + idx]);
    split2(ssq * (w - 2.f * a * v * v), &oh[2 * BNTOT + idx], &ol[2 * BNTOT + idx]);
}

__global__ void sincos_kernel(const float* __restrict__ out)
{
    int idx = blockIdx.x * blockDim.x + threadIdx.x;
    if (idx >= BNTOT) return;
    float s, c;
    sincosf(out[idx], &s, &c);
    split2(s, &g_SCh[idx],         &g_SCl[idx]);
    split2(c, &g_SCh[BNTOT + idx], &g_SCl[BNTOT + idx]);
}

__global__ void final_kernel(float* __restrict__ out, const float* __restrict__ lm,
                             const float* __restrict__ ld, const float* __restrict__ p)
{
    int idx = blockIdx.x * blockDim.x + threadIdx.x;
    if (idx >= BNTOT) return;
    int col = idx & (NB - 1);
    float ot  = out[BNTOT + idx];
    float ott = out[2 * BNTOT + idx];
    float s, c;
    sincosf(out[idx], &s, &c);
    float conn = s * g_SS[BNTOT + idx] - c * g_SS[idx];
    out[2 * BNTOT + idx] = lm[col] * ott + ld[col] * ot + conn - p[idx];
}

// ---------------------------------------------------------------------------
// Launch
// ---------------------------------------------------------------------------
extern "C" void kernel_launch(void* const* d_in, const int* in_sizes, int n_in,
                              void* d_out, int out_size)
{
    const float* t    = (const float*)d_in[0];
    const float* p    = (const float*)d_in[1];
    const float* W0   = (const float*)d_in[2];
    const float* b0   = (const float*)d_in[3];
    const float* W1   = (const float*)d_in[4];
    const float* b1   = (const float*)d_in[5];
    const float* W2   = (const float*)d_in[6];
    const float* b2   = (const float*)d_in[7];
    const float* Wout = (const float*)d_in[8];
    const float* bout = (const float*)d_in[9];
    const float* lm   = (const float*)d_in[10];
    const float* ld   = (const float*)d_in[11];
    const float* lb   = (const float*)d_in[12];
    const float* pl   = (const float*)d_in[13];
    const float* pu   = (const float*)d_in[14];
    float* out = (float*)d_out;

    __nv_bfloat16 *pXh,*pXl,*pW0h,*pW0l,*pW1h,*pW1l,*pW2h,*pW2l,*pWoh,*pWol,*pLbh,*pLbl;
    __nv_bfloat16 *pAh,*pAl,*pBh,*pBl,*pSCh,*pSCl;
    float *pU,*pSS;
    cudaGetSymbolAddress((void**)&pXh, g_Xh);   cudaGetSymbolAddress((void**)&pXl, g_Xl);
    cudaGetSymbolAddress((void**)&pW0h, g_W0Th);cudaGetSymbolAddress((void**)&pW0l, g_W0Tl);
    cudaGetSymbolAddress((void**)&pW1h, g_W1Th);cudaGetSymbolAddress((void**)&pW1l, g_W1Tl);
    cudaGetSymbolAddress((void**)&pW2h, g_W2Th);cudaGetSymbolAddress((void**)&pW2l, g_W2Tl);
    cudaGetSymbolAddress((void**)&pWoh, g_WoTh);cudaGetSymbolAddress((void**)&pWol, g_WoTl);
    cudaGetSymbolAddress((void**)&pLbh, g_Lbh); cudaGetSymbolAddress((void**)&pLbl, g_Lbl);
    cudaGetSymbolAddress((void**)&pAh, g_Ah);   cudaGetSymbolAddress((void**)&pAl, g_Al);
    cudaGetSymbolAddress((void**)&pBh, g_Bh);   cudaGetSymbolAddress((void**)&pBl, g_Bl);
    cudaGetSymbolAddress((void**)&pSCh, g_SCh); cudaGetSymbolAddress((void**)&pSCl, g_SCl);
    cudaGetSymbolAddress((void**)&pU, g_U);     cudaGetSymbolAddress((void**)&pSS, g_SS);

    const int EW = 256;
    // prep
    build_x_kernel<<<(BATCH * KP + EW - 1) / EW, EW>>>(t, p, pl, pu);
    wsplitT_kernel<<<(HD * KP + EW - 1) / EW, EW>>>(W0, pW0h, pW0l, 1 + NB, HD, KP);
    wsplitT_kernel<<<(HD * HD + EW - 1) / EW, EW>>>(W1, pW1h, pW1l, HD, HD, HD);
    wsplitT_kernel<<<(HD * HD + EW - 1) / EW, EW>>>(W2, pW2h, pW2l, HD, HD, HD);
    wsplitT_kernel<<<(HD * NB + EW - 1) / EW, EW>>>(Wout, pWoh, pWol, HD, NB, HD);
    lbsplit_kernel<<<(NB * NB + EW - 1) / EW, EW>>>(lb);

    // layer 0: [1024,576] x [512,576]^T + b0
    hmma_gemm<<<dim3(HD / 128, BATCH / 128), 256>>>(pXh, pXl, pW0h, pW0l, pU, BATCH, HD, KP, b0, BATCH);
    act0_kernel<<<(BNTOT + EW - 1) / EW, EW>>>(W0);

    // layer 1: [3072,512] x W1^T (+b1 on value stream rows)
    hmma_gemm<<<dim3(HD / 128, 3 * BATCH / 128), 256>>>(pAh, pAl, pW1h, pW1l, pU, 3 * BATCH, HD, HD, b1, BATCH);
    act12_kernel<<<(BNTOT + EW - 1) / EW, EW>>>(pU, pBh, pBl);

    // layer 2
    hmma_gemm<<<dim3(HD / 128, 3 * BATCH / 128), 256>>>(pBh, pBl, pW2h, pW2l, pU, 3 * BATCH, HD, HD, b2, BATCH);
    act12_kernel<<<(BNTOT + EW - 1) / EW, EW>>>(pU, pAh, pAl);

    // output layer -> d_out [out | out_t | out_tt]
    hmma_gemm<<<dim3(NB / 128, 3 * BATCH / 128), 256>>>(pAh, pAl, pWoh, pWol, out, 3 * BATCH, NB, HD, bout, BATCH);

    // connectivity: [sin;cos] [2048,512] x lambda_b^T (g_Lb rows are lambda_b[i][:])
    sincos_kernel<<<(BNTOT + EW - 1) / EW, EW>>>(out);
    hmma_gemm<<<dim3(NB / 128, 2 * BATCH / 128), 256>>>(pSCh, pSCl, pLbh, pLbl, pSS, 2 * BATCH, NB, NB, nullptr, 0);

    // physics residual (overwrites out_tt slot)
    final_kernel<<<(BNTOT + EW - 1) / EW, EW>>>(out, lm, ld, p);
}

// round 5
// speedup vs baseline: 1.2764x; 1.0746x over previous
#include <cuda_runtime.h>
#include <cuda_bf16.h>
#include <math.h>
#include <stdint.h>

// Problem dims
#define BATCH 1024
#define NB    512
#define HD    512
#define KP    576            // padded input dim (1+512 -> 576 = 18*32)
#define BNTOT (BATCH*NB)     // 524288

// ---------------------------------------------------------------------------
// Scratch (device globals)
// ---------------------------------------------------------------------------
__device__ __nv_bfloat16 g_Xh[BATCH*KP],  g_Xl[BATCH*KP];
__device__ __nv_bfloat16 g_W0Th[HD*KP],   g_W0Tl[HD*KP];     // W0^T padded [512 x 576]
__device__ __nv_bfloat16 g_W1Th[HD*HD],   g_W1Tl[HD*HD];
__device__ __nv_bfloat16 g_W2Th[HD*HD],   g_W2Tl[HD*HD];
__device__ __nv_bfloat16 g_WoTh[HD*NB],   g_WoTl[HD*NB];     // Wout^T [512 x 512]
__device__ __nv_bfloat16 g_Lbh[NB*NB],    g_Lbl[NB*NB];      // lambda_b rows (acts as B^T)
__device__ __nv_bfloat16 g_Ah[3*BNTOT],   g_Al[3*BNTOT];     // activations ping
__device__ __nv_bfloat16 g_Bh[3*BNTOT],   g_Bl[3*BNTOT];     // activations pong
__device__ __nv_bfloat16 g_SCh[2*BNTOT],  g_SCl[2*BNTOT];    // [sin ; cos]
__device__ float g_U [3*BNTOT];                              // pre-activations fp32
__device__ float g_SS[2*BNTOT];                              // [sin@LbT ; cos@LbT]

__device__ __forceinline__ void split2(float x, __nv_bfloat16* h, __nv_bfloat16* l) {
    __nv_bfloat16 hi = __float2bfloat16_rn(x);
    *h = hi;
    *l = __float2bfloat16_rn(x - __bfloat162float(hi));
}

__device__ __forceinline__ uint32_t smem_u32(const void* p) {
    uint32_t a;
    asm("{ .reg .u64 t; cvta.to.shared.u64 t, %1; cvt.u32.u64 %0, t; }" : "=r"(a) : "l"(p));
    return a;
}

__device__ __forceinline__ void mma_bf16(float* d, const uint32_t* a, uint32_t b0, uint32_t b1) {
    asm volatile(
        "mma.sync.aligned.m16n8k16.row.col.f32.bf16.bf16.f32 "
        "{%0,%1,%2,%3},{%4,%5,%6,%7},{%8,%9},{%0,%1,%2,%3};"
        : "+f"(d[0]), "+f"(d[1]), "+f"(d[2]), "+f"(d[3])
        : "r"(a[0]), "r"(a[1]), "r"(a[2]), "r"(a[3]), "r"(b0), "r"(b1));
}

// ---------------------------------------------------------------------------
// HMMA split-bf16 GEMM: C[M,N] = A[M,K] * B^T  (B stored [N,K] row-major)
// C = Ah*Bh + Ah*Bl + Al*Bh  via 3 K-segments. CTA tile 128x128, Kc=32.
// 8 warps: warp (wm=wid&3, wn=wid>>2) owns 32(M) x 64(N).
// 4-stage cp.async pipeline, dynamic smem 64KB (4 x (A 8KB + B 8KB)).
// XOR swizzle chunk^((row>>1)&3) -> conflict-free STS and ldmatrix.
// ---------------------------------------------------------------------------
#define STG_BYTES 16384

__global__ void __launch_bounds__(256)
hmma_gemm(const __nv_bfloat16* __restrict__ Ah, const __nv_bfloat16* __restrict__ Al,
          const __nv_bfloat16* __restrict__ Bh, const __nv_bfloat16* __restrict__ Bl,
          float* __restrict__ C, int M, int N, int K,
          const float* __restrict__ bias, int bias_rows)
{
    extern __shared__ __align__(1024) char smem[];
    const uint32_t sb = smem_u32(smem);
    const int tid = threadIdx.x;
    const int lane = tid & 31;
    const int wid = tid >> 5;
    const int wm = wid & 3;          // M direction (4 x 32 = 128)
    const int wn = wid >> 2;         // N direction (2 x 64 = 128)
    const int m0 = blockIdx.y * 128;
    const int n0 = blockIdx.x * 128;
    const int ncK = K >> 5;
    const int TOT = 3 * ncK;

    float acc[2][8][4];
#pragma unroll
    for (int i = 0; i < 2; i++)
#pragma unroll
        for (int j = 0; j < 8; j++)
#pragma unroll
            for (int q = 0; q < 4; q++) acc[i][j][q] = 0.f;

    const int ldRow = tid >> 2;          // 0..63  (x2 => 128 rows)
    const int ldCh  = tid & 3;           // 16B chunk within 64B row

    auto load_stage = [&](int c, int stg) {
        const int s  = c / ncK;
        const int kk = c - s * ncK;
        const __nv_bfloat16* Ap = (s < 2) ? Ah : Al;
        const __nv_bfloat16* Bp = (s == 1) ? Bl : Bh;
        const int kbase = kk << 5;
        const uint32_t abase = sb + stg * STG_BYTES;
        const uint32_t bbase = abase + 8192;
#pragma unroll
        for (int h = 0; h < 2; h++) {
            int row = ldRow + h * 64;
            uint32_t sa = abase + row * 64 + ((ldCh ^ ((row >> 1) & 3)) << 4);
            const void* ga = Ap + (size_t)(m0 + row) * K + kbase + ldCh * 8;
            asm volatile("cp.async.cg.shared.global [%0], [%1], 16;" :: "r"(sa), "l"(ga));
        }
#pragma unroll
        for (int h = 0; h < 2; h++) {
            int row = ldRow + h * 64;
            uint32_t sa = bbase + row * 64 + ((ldCh ^ ((row >> 1) & 3)) << 4);
            const void* ga = Bp + (size_t)(n0 + row) * K + kbase + ldCh * 8;
            asm volatile("cp.async.cg.shared.global [%0], [%1], 16;" :: "r"(sa), "l"(ga));
        }
    };

    // prologue: 3 stages in flight
#pragma unroll
    for (int c0 = 0; c0 < 3; c0++) {
        load_stage(c0, c0);
        asm volatile("cp.async.commit_group;" ::: "memory");
    }

    for (int c = 0; c < TOT; c++) {
        asm volatile("cp.async.wait_group 2;" ::: "memory");
        __syncthreads();
        // refill: stage c+3 into buffer (c+3)&3 (== (c-1)&3, drained last iter)
        if (c + 3 < TOT) load_stage(c + 3, (c + 3) & 3);
        asm volatile("cp.async.commit_group;" ::: "memory");

        const uint32_t abase = sb + (c & 3) * STG_BYTES;
        const uint32_t bbase = abase + 8192;

#pragma unroll
        for (int kb = 0; kb < 2; kb++) {
            uint32_t a[2][4];
#pragma unroll
            for (int i = 0; i < 2; i++) {
                int row = wm * 32 + i * 16 + (lane & 15);
                int ch  = kb * 2 + (lane >> 4);
                uint32_t ad = abase + row * 64 + ((ch ^ ((row >> 1) & 3)) << 4);
                asm volatile("ldmatrix.sync.aligned.m8n8.x4.shared.b16 {%0,%1,%2,%3}, [%4];"
                             : "=r"(a[i][0]), "=r"(a[i][1]), "=r"(a[i][2]), "=r"(a[i][3])
                             : "r"(ad));
            }
#pragma unroll
            for (int j = 0; j < 4; j++) {
                uint32_t b[4];
                int rn  = (lane & 7) + ((lane >> 4) << 3);
                int row = wn * 64 + j * 16 + rn;
                int ch  = kb * 2 + ((lane >> 3) & 1);
                uint32_t bd = bbase + row * 64 + ((ch ^ ((row >> 1) & 3)) << 4);
                asm volatile("ldmatrix.sync.aligned.m8n8.x4.shared.b16 {%0,%1,%2,%3}, [%4];"
                             : "=r"(b[0]), "=r"(b[1]), "=r"(b[2]), "=r"(b[3])
                             : "r"(bd));
#pragma unroll
                for (int i = 0; i < 2; i++) {
                    mma_bf16(acc[i][2 * j],     a[i], b[0], b[1]);
                    mma_bf16(acc[i][2 * j + 1], a[i], b[2], b[3]);
                }
            }
        }
    }

    // epilogue
    const int gr  = lane >> 2;           // row within 8
    const int cp2 = (lane & 3) * 2;      // col pair
#pragma unroll
    for (int i = 0; i < 2; i++) {
#pragma unroll
        for (int j8 = 0; j8 < 8; j8++) {
            int col = n0 + wn * 64 + j8 * 8 + cp2;
            int r0  = m0 + wm * 32 + i * 16 + gr;
            float bx = 0.f, by = 0.f;
            if (bias) { bx = bias[col]; by = bias[col + 1]; }
#pragma unroll
            for (int rr = 0; rr < 2; rr++) {
                int row = r0 + rr * 8;
                float2 v;
                v.x = acc[i][j8][2 * rr + 0];
                v.y = acc[i][j8][2 * rr + 1];
                if (bias && row < bias_rows) { v.x += bx; v.y += by; }
                *reinterpret_cast<float2*>(&C[(size_t)row * N + col]) = v;
            }
        }
    }
}

// ---------------------------------------------------------------------------
// Elementwise / prep kernels
// ---------------------------------------------------------------------------
__global__ void build_x_kernel(const float* __restrict__ t, const float* __restrict__ p,
                               const float* __restrict__ pl, const float* __restrict__ pu)
{
    int idx = blockIdx.x * blockDim.x + threadIdx.x;
    if (idx >= BATCH * KP) return;
    int row = idx / KP, col = idx - row * KP;
    float v;
    if (col == 0) v = 0.2f * t[row] - 1.0f;
    else if (col <= NB) {
        int j = col - 1;
        float lo = pl[j], hi = pu[j];
        v = (hi == lo) ? 0.f : (2.f * (p[row * NB + j] - lo) / (hi - lo) - 1.f);
    } else v = 0.f;
    split2(v, &g_Xh[idx], &g_Xl[idx]);
}

// Tiled transpose + split: oh/ol[n*Kout+k] = split( k<Kin ? W[k*Nw+n] : 0 )
// grid (Kout/32, Nw/32), block (32, 8). Coalesced on both sides.
__global__ void wsplitT_tile(const float* __restrict__ W,
                             __nv_bfloat16* __restrict__ oh, __nv_bfloat16* __restrict__ ol,
                             int Kin, int Nw, int Kout)
{
    __shared__ float tile[32][33];
    const int tx = threadIdx.x, ty = threadIdx.y;
    const int kb = blockIdx.x * 32, nb = blockIdx.y * 32;
#pragma unroll
    for (int i = 0; i < 32; i += 8) {
        int k = kb + ty + i;
        tile[ty + i][tx] = (k < Kin) ? W[(size_t)k * Nw + nb + tx] : 0.f;
    }
    __syncthreads();
#pragma unroll
    for (int i = 0; i < 32; i += 8) {
        int n = nb + ty + i;
        size_t o = (size_t)n * Kout + kb + tx;
        split2(tile[tx][ty + i], &oh[o], &ol[o]);
    }
}

__global__ void lbsplit_kernel(const float* __restrict__ lb)
{
    int idx = blockIdx.x * blockDim.x + threadIdx.x;
    if (idx >= NB * NB) return;
    split2(lb[idx], &g_Lbh[idx], &g_Lbl[idx]);
}

__global__ void act0_kernel(const float* __restrict__ W0)
{
    int idx = blockIdx.x * blockDim.x + threadIdx.x;
    if (idx >= BNTOT) return;
    int col = idx & (HD - 1);
    float u = g_U[idx];
    float a = tanhf(u);
    float ssq = 1.f - a * a;
    float gth = 0.2f * W0[col];      // W0 row 0
    split2(a,                          &g_Ah[idx],             &g_Al[idx]);
    split2(ssq * gth,                  &g_Ah[BNTOT + idx],     &g_Al[BNTOT + idx]);
    split2(-2.f * a * ssq * gth * gth, &g_Ah[2 * BNTOT + idx], &g_Al[2 * BNTOT + idx]);
}

__global__ void act12_kernel(const float* __restrict__ U,
                             __nv_bfloat16* __restrict__ oh, __nv_bfloat16* __restrict__ ol)
{
    int idx = blockIdx.x * blockDim.x + threadIdx.x;
    if (idx >= BNTOT) return;
    float u = U[idx];
    float v = U[BNTOT + idx];
    float w = U[2 * BNTOT + idx];
    float a = tanhf(u);
    float ssq = 1.f - a * a;
    split2(a,                           &oh[idx],             &ol[idx]);
    split2(ssq * v,                     &oh[BNTOT + idx],     &ol[BNTOT + idx]);
    split2(ssq * (w - 2.f * a * v * v), &oh[2 * BNTOT + idx], &ol[2 * BNTOT + idx]);
}

__global__ void sincos_kernel(const float* __restrict__ out)
{
    int idx = blockIdx.x * blockDim.x + threadIdx.x;
    if (idx >= BNTOT) return;
    float s, c;
    sincosf(out[idx], &s, &c);
    split2(s, &g_SCh[idx],         &g_SCl[idx]);
    split2(c, &g_SCh[BNTOT + idx], &g_SCl[BNTOT + idx]);
}

__global__ void final_kernel(float* __restrict__ out, const float* __restrict__ lm,
                             const float* __restrict__ ld, const float* __restrict__ p)
{
    int idx = blockIdx.x * blockDim.x + threadIdx.x;
    if (idx >= BNTOT) return;
    int col = idx & (NB - 1);
    float ot  = out[BNTOT + idx];
    float ott = out[2 * BNTOT + idx];
    float s, c;
    sincosf(out[idx], &s, &c);
    float conn = s * g_SS[BNTOT + idx] - c * g_SS[idx];
    out[2 * BNTOT + idx] = lm[col] * ott + ld[col] * ot + conn - p[idx];
}

// ---------------------------------------------------------------------------
// Launch
// ---------------------------------------------------------------------------
extern "C" void kernel_launch(void* const* d_in, const int* in_sizes, int n_in,
                              void* d_out, int out_size)
{
    const float* t    = (const float*)d_in[0];
    const float* p    = (const float*)d_in[1];
    const float* W0   = (const float*)d_in[2];
    const float* b0   = (const float*)d_in[3];
    const float* W1   = (const float*)d_in[4];
    const float* b1   = (const float*)d_in[5];
    const float* W2   = (const float*)d_in[6];
    const float* b2   = (const float*)d_in[7];
    const float* Wout = (const float*)d_in[8];
    const float* bout = (const float*)d_in[9];
    const float* lm   = (const float*)d_in[10];
    const float* ld   = (const float*)d_in[11];
    const float* lb   = (const float*)d_in[12];
    const float* pl   = (const float*)d_in[13];
    const float* pu   = (const float*)d_in[14];
    float* out = (float*)d_out;

    cudaFuncSetAttribute(hmma_gemm, cudaFuncAttributeMaxDynamicSharedMemorySize, 4 * STG_BYTES);
    const int GSM = 4 * STG_BYTES;

    __nv_bfloat16 *pXh,*pXl,*pW0h,*pW0l,*pW1h,*pW1l,*pW2h,*pW2l,*pWoh,*pWol,*pLbh,*pLbl;
    __nv_bfloat16 *pAh,*pAl,*pBh,*pBl,*pSCh,*pSCl;
    float *pU,*pSS;
    cudaGetSymbolAddress((void**)&pXh, g_Xh);   cudaGetSymbolAddress((void**)&pXl, g_Xl);
    cudaGetSymbolAddress((void**)&pW0h, g_W0Th);cudaGetSymbolAddress((void**)&pW0l, g_W0Tl);
    cudaGetSymbolAddress((void**)&pW1h, g_W1Th);cudaGetSymbolAddress((void**)&pW1l, g_W1Tl);
    cudaGetSymbolAddress((void**)&pW2h, g_W2Th);cudaGetSymbolAddress((void**)&pW2l, g_W2Tl);
    cudaGetSymbolAddress((void**)&pWoh, g_WoTh);cudaGetSymbolAddress((void**)&pWol, g_WoTl);
    cudaGetSymbolAddress((void**)&pLbh, g_Lbh); cudaGetSymbolAddress((void**)&pLbl, g_Lbl);
    cudaGetSymbolAddress((void**)&pAh, g_Ah);   cudaGetSymbolAddress((void**)&pAl, g_Al);
    cudaGetSymbolAddress((void**)&pBh, g_Bh);   cudaGetSymbolAddress((void**)&pBl, g_Bl);
    cudaGetSymbolAddress((void**)&pSCh, g_SCh); cudaGetSymbolAddress((void**)&pSCl, g_SCl);
    cudaGetSymbolAddress((void**)&pU, g_U);     cudaGetSymbolAddress((void**)&pSS, g_SS);

    const int EW = 256;
    // prep
    build_x_kernel<<<(BATCH * KP + EW - 1) / EW, EW>>>(t, p, pl, pu);
    {
        dim3 tb(32, 8);
        wsplitT_tile<<<dim3(KP / 32, HD / 32), tb>>>(W0, pW0h, pW0l, 1 + NB, HD, KP);
        wsplitT_tile<<<dim3(HD / 32, HD / 32), tb>>>(W1, pW1h, pW1l, HD, HD, HD);
        wsplitT_tile<<<dim3(HD / 32, HD / 32), tb>>>(W2, pW2h, pW2l, HD, HD, HD);
        wsplitT_tile<<<dim3(HD / 32, NB / 32), tb>>>(Wout, pWoh, pWol, HD, NB, HD);
    }
    lbsplit_kernel<<<(NB * NB + EW - 1) / EW, EW>>>(lb);

    // layer 0: [1024,576] x [512,576]^T + b0
    hmma_gemm<<<dim3(HD / 128, BATCH / 128), 256, GSM>>>(pXh, pXl, pW0h, pW0l, pU, BATCH, HD, KP, b0, BATCH);
    act0_kernel<<<(BNTOT + EW - 1) / EW, EW>>>(W0);

    // layer 1: [3072,512] x W1^T (+b1 on value stream rows)
    hmma_gemm<<<dim3(HD / 128, 3 * BATCH / 128), 256, GSM>>>(pAh, pAl, pW1h, pW1l, pU, 3 * BATCH, HD, HD, b1, BATCH);
    act12_kernel<<<(BNTOT + EW - 1) / EW, EW>>>(pU, pBh, pBl);

    // layer 2
    hmma_gemm<<<dim3(HD / 128, 3 * BATCH / 128), 256, GSM>>>(pBh, pBl, pW2h, pW2l, pU, 3 * BATCH, HD, HD, b2, BATCH);
    act12_kernel<<<(BNTOT + EW - 1) / EW, EW>>>(pU, pAh, pAl);

    // output layer -> d_out [out | out_t | out_tt]
    hmma_gemm<<<dim3(NB / 128, 3 * BATCH / 128), 256, GSM>>>(pAh, pAl, pWoh, pWol, out, 3 * BATCH, NB, HD, bout, BATCH);

    // connectivity: [sin;cos] [2048,512] x lambda_b^T
    sincos_kernel<<<(BNTOT + EW - 1) / EW, EW>>>(out);
    hmma_gemm<<<dim3(NB / 128, 2 * BATCH / 128), 256, GSM>>>(pSCh, pSCl, pLbh, pLbl, pSS, 2 * BATCH, NB, NB, nullptr, 0);

    // physics residual (overwrites out_tt slot)
    final_kernel<<<(BNTOT + EW - 1) / EW, EW>>>(out, lm, ld, p);
}

// round 6
// speedup vs baseline: 2.3074x; 1.8077x over previous
#include <cuda_runtime.h>
#include <cuda_bf16.h>
#include <math.h>
#include <stdint.h>

// Problem dims
#define BATCH 1024
#define NB    512
#define HD    512
#define KP    576            // padded input dim (1+512 -> 576 = 18*32)
#define BNTOT (BATCH*NB)     // 524288

// ---------------------------------------------------------------------------
// Scratch (device globals)
// ---------------------------------------------------------------------------
__device__ __nv_bfloat16 g_Xh[BATCH*KP],  g_Xl[BATCH*KP];
__device__ __nv_bfloat16 g_W0Th[HD*KP],   g_W0Tl[HD*KP];     // W0^T padded [512 x 576]
__device__ __nv_bfloat16 g_W1Th[HD*HD],   g_W1Tl[HD*HD];
__device__ __nv_bfloat16 g_W2Th[HD*HD],   g_W2Tl[HD*HD];
__device__ __nv_bfloat16 g_WoTh[HD*NB],   g_WoTl[HD*NB];     // Wout^T [512 x 512]
__device__ __nv_bfloat16 g_Lbh[NB*NB],    g_Lbl[NB*NB];      // lambda_b rows
__device__ __nv_bfloat16 g_Ah[3*BNTOT],   g_Al[3*BNTOT];     // activations ping
__device__ __nv_bfloat16 g_Bh[3*BNTOT],   g_Bl[3*BNTOT];     // activations pong
__device__ __nv_bfloat16 g_SCh[2*BNTOT],  g_SCl[2*BNTOT];    // [sin ; cos] hi/lo
__device__ float g_P  [3*3*BNTOT];   // GEMM partials: segment s at offset s*M*N
__device__ float g_SSp[3*2*BNTOT];   // conn GEMM partials

__device__ __forceinline__ void split2(float x, __nv_bfloat16* h, __nv_bfloat16* l) {
    __nv_bfloat16 hi = __float2bfloat16_rn(x);
    *h = hi;
    *l = __float2bfloat16_rn(x - __bfloat162float(hi));
}

__device__ __forceinline__ uint32_t smem_u32(const void* p) {
    uint32_t a;
    asm("{ .reg .u64 t; cvta.to.shared.u64 t, %1; cvt.u32.u64 %0, t; }" : "=r"(a) : "l"(p));
    return a;
}

__device__ __forceinline__ void mma_bf16(float* d, const uint32_t* a, uint32_t b0, uint32_t b1) {
    asm volatile(
        "mma.sync.aligned.m16n8k16.row.col.f32.bf16.bf16.f32 "
        "{%0,%1,%2,%3},{%4,%5,%6,%7},{%8,%9},{%0,%1,%2,%3};"
        : "+f"(d[0]), "+f"(d[1]), "+f"(d[2]), "+f"(d[3])
        : "r"(a[0]), "r"(a[1]), "r"(a[2]), "r"(a[3]), "r"(b0), "r"(b1));
}

// ---------------------------------------------------------------------------
// HMMA split-bf16 GEMM, z-split over compensation segments.
// blockIdx.z = s in {0,1,2}: s=0: Ah*Bh (+bias), s=1: Ah*Bl, s=2: Al*Bh.
// Each segment writes its own fp32 partial at Cpart + s*M*N; consumers sum.
// CTA tile 128x128, Kc=32, 3-stage cp.async pipeline (48KB), 2 CTAs/SM.
// ---------------------------------------------------------------------------
#define STG_BYTES 16384

__global__ void __launch_bounds__(256, 2)
hmma_gemm_z(const __nv_bfloat16* __restrict__ Ah, const __nv_bfloat16* __restrict__ Al,
            const __nv_bfloat16* __restrict__ Bh, const __nv_bfloat16* __restrict__ Bl,
            float* __restrict__ Cpart, int M, int N, int K,
            const float* __restrict__ bias, int bias_rows)
{
    extern __shared__ __align__(1024) char smem[];
    const uint32_t sb = smem_u32(smem);
    const int tid = threadIdx.x;
    const int lane = tid & 31;
    const int wid = tid >> 5;
    const int wm = wid & 3;          // M direction (4 x 32 = 128)
    const int wn = wid >> 2;         // N direction (2 x 64 = 128)
    const int m0 = blockIdx.y * 128;
    const int n0 = blockIdx.x * 128;
    const int s  = blockIdx.z;
    const int ncK = K >> 5;

    const __nv_bfloat16* __restrict__ Ap = (s < 2) ? Ah : Al;
    const __nv_bfloat16* __restrict__ Bp = (s == 1) ? Bl : Bh;
    float* __restrict__ C = Cpart + (size_t)s * M * N;
    const float* bp = (s == 0) ? bias : nullptr;

    float acc[2][8][4];
#pragma unroll
    for (int i = 0; i < 2; i++)
#pragma unroll
        for (int j = 0; j < 8; j++)
#pragma unroll
            for (int q = 0; q < 4; q++) acc[i][j][q] = 0.f;

    const int ldRow = tid >> 2;          // 0..63  (x2 => 128 rows)
    const int ldCh  = tid & 3;           // 16B chunk within 64B row

    auto load_stage = [&](int kk, int stg) {
        const int kbase = kk << 5;
        const uint32_t abase = sb + stg * STG_BYTES;
        const uint32_t bbase = abase + 8192;
#pragma unroll
        for (int h = 0; h < 2; h++) {
            int row = ldRow + h * 64;
            uint32_t sa = abase + row * 64 + ((ldCh ^ ((row >> 1) & 3)) << 4);
            const void* ga = Ap + (size_t)(m0 + row) * K + kbase + ldCh * 8;
            asm volatile("cp.async.cg.shared.global [%0], [%1], 16;" :: "r"(sa), "l"(ga));
        }
#pragma unroll
        for (int h = 0; h < 2; h++) {
            int row = ldRow + h * 64;
            uint32_t sa = bbase + row * 64 + ((ldCh ^ ((row >> 1) & 3)) << 4);
            const void* ga = Bp + (size_t)(n0 + row) * K + kbase + ldCh * 8;
            asm volatile("cp.async.cg.shared.global [%0], [%1], 16;" :: "r"(sa), "l"(ga));
        }
    };

    // prologue: 2 stages in flight
    load_stage(0, 0);
    asm volatile("cp.async.commit_group;" ::: "memory");
    load_stage(1, 1);
    asm volatile("cp.async.commit_group;" ::: "memory");

    int cbuf = 0, nbuf = 2;
    for (int c = 0; c < ncK; c++) {
        asm volatile("cp.async.wait_group 1;" ::: "memory");
        __syncthreads();
        if (c + 2 < ncK) load_stage(c + 2, nbuf);
        asm volatile("cp.async.commit_group;" ::: "memory");

        const uint32_t abase = sb + cbuf * STG_BYTES;
        const uint32_t bbase = abase + 8192;

#pragma unroll
        for (int kb = 0; kb < 2; kb++) {
            uint32_t a[2][4];
#pragma unroll
            for (int i = 0; i < 2; i++) {
                int row = wm * 32 + i * 16 + (lane & 15);
                int ch  = kb * 2 + (lane >> 4);
                uint32_t ad = abase + row * 64 + ((ch ^ ((row >> 1) & 3)) << 4);
                asm volatile("ldmatrix.sync.aligned.m8n8.x4.shared.b16 {%0,%1,%2,%3}, [%4];"
                             : "=r"(a[i][0]), "=r"(a[i][1]), "=r"(a[i][2]), "=r"(a[i][3])
                             : "r"(ad));
            }
#pragma unroll
            for (int j = 0; j < 4; j++) {
                uint32_t b[4];
                int rn  = (lane & 7) + ((lane >> 4) << 3);
                int row = wn * 64 + j * 16 + rn;
                int ch  = kb * 2 + ((lane >> 3) & 1);
                uint32_t bd = bbase + row * 64 + ((ch ^ ((row >> 1) & 3)) << 4);
                asm volatile("ldmatrix.sync.aligned.m8n8.x4.shared.b16 {%0,%1,%2,%3}, [%4];"
                             : "=r"(b[0]), "=r"(b[1]), "=r"(b[2]), "=r"(b[3])
                             : "r"(bd));
#pragma unroll
                for (int i = 0; i < 2; i++) {
                    mma_bf16(acc[i][2 * j],     a[i], b[0], b[1]);
                    mma_bf16(acc[i][2 * j + 1], a[i], b[2], b[3]);
                }
            }
        }
        cbuf = (cbuf == 2) ? 0 : cbuf + 1;
        nbuf = (nbuf == 2) ? 0 : nbuf + 1;
    }

    // epilogue
    const int gr  = lane >> 2;           // row within 8
    const int cp2 = (lane & 3) * 2;      // col pair
#pragma unroll
    for (int i = 0; i < 2; i++) {
#pragma unroll
        for (int j8 = 0; j8 < 8; j8++) {
            int col = n0 + wn * 64 + j8 * 8 + cp2;
            int r0  = m0 + wm * 32 + i * 16 + gr;
            float bx = 0.f, by = 0.f;
            if (bp) { bx = bp[col]; by = bp[col + 1]; }
#pragma unroll
            for (int rr = 0; rr < 2; rr++) {
                int row = r0 + rr * 8;
                float2 v;
                v.x = acc[i][j8][2 * rr + 0];
                v.y = acc[i][j8][2 * rr + 1];
                if (bp && row < bias_rows) { v.x += bx; v.y += by; }
                *reinterpret_cast<float2*>(&C[(size_t)row * N + col]) = v;
            }
        }
    }
}

// ---------------------------------------------------------------------------
// Fused prep: z<4 -> tiled transpose+split of W0/W1/W2/Wout; z==4 -> lambda_b
// straight split. grid (18, 16, 5), block (32, 8).
// ---------------------------------------------------------------------------
__global__ void prep_all(const float* __restrict__ W0, const float* __restrict__ W1,
                         const float* __restrict__ W2, const float* __restrict__ Wo,
                         const float* __restrict__ lb)
{
    const int tx = threadIdx.x, ty = threadIdx.y;
    const int kb = blockIdx.x * 32, nb = blockIdx.y * 32;
    const int z = blockIdx.z;

    if (z == 4) {  // lambda_b straight split
        if (kb >= NB) return;
#pragma unroll
        for (int i = 0; i < 32; i += 8) {
            size_t o = (size_t)(nb + ty + i) * NB + kb + tx;
            split2(lb[o], &g_Lbh[o], &g_Lbl[o]);
        }
        return;
    }

    const float* W; __nv_bfloat16 *oh, *ol; int Kin, Kout;
    if (z == 0)      { W = W0; oh = g_W0Th; ol = g_W0Tl; Kin = NB + 1; Kout = KP; }
    else if (z == 1) { W = W1; oh = g_W1Th; ol = g_W1Tl; Kin = HD;     Kout = HD; }
    else if (z == 2) { W = W2; oh = g_W2Th; ol = g_W2Tl; Kin = HD;     Kout = HD; }
    else             { W = Wo; oh = g_WoTh; ol = g_WoTl; Kin = HD;     Kout = HD; }
    if (kb >= Kout) return;

    __shared__ float tile[32][33];
#pragma unroll
    for (int i = 0; i < 32; i += 8) {
        int k = kb + ty + i;
        tile[ty + i][tx] = (k < Kin) ? W[(size_t)k * HD + nb + tx] : 0.f;
    }
    __syncthreads();
#pragma unroll
    for (int i = 0; i < 32; i += 8) {
        int n = nb + ty + i;
        size_t o = (size_t)n * Kout + kb + tx;
        split2(tile[tx][ty + i], &oh[o], &ol[o]);
    }
}

// ---------------------------------------------------------------------------
// Elementwise kernels
// ---------------------------------------------------------------------------
__global__ void build_x_kernel(const float* __restrict__ t, const float* __restrict__ p,
                               const float* __restrict__ pl, const float* __restrict__ pu)
{
    int idx = blockIdx.x * blockDim.x + threadIdx.x;
    if (idx >= BATCH * KP) return;
    int row = idx / KP, col = idx - row * KP;
    float v;
    if (col == 0) v = 0.2f * t[row] - 1.0f;
    else if (col <= NB) {
        int j = col - 1;
        float lo = pl[j], hi = pu[j];
        v = (hi == lo) ? 0.f : (2.f * (p[row * NB + j] - lo) / (hi - lo) - 1.f);
    } else v = 0.f;
    split2(v, &g_Xh[idx], &g_Xl[idx]);
}

// layer0 partials: M*N = BNTOT per segment
__global__ void act0_kernel(const float* __restrict__ W0)
{
    int idx = blockIdx.x * blockDim.x + threadIdx.x;
    if (idx >= BNTOT) return;
    int col = idx & (HD - 1);
    float u = g_P[idx] + g_P[BNTOT + idx] + g_P[2 * BNTOT + idx];
    float a = tanhf(u);
    float ssq = 1.f - a * a;
    float gth = 0.2f * W0[col];      // W0 row 0
    split2(a,                          &g_Ah[idx],             &g_Al[idx]);
    split2(ssq * gth,                  &g_Ah[BNTOT + idx],     &g_Al[BNTOT + idx]);
    split2(-2.f * a * ssq * gth * gth, &g_Ah[2 * BNTOT + idx], &g_Al[2 * BNTOT + idx]);
}

// layers 1/2 partials: M*N = 3*BNTOT per segment; stream t at t*BNTOT
__global__ void act12_kernel(__nv_bfloat16* __restrict__ oh, __nv_bfloat16* __restrict__ ol)
{
    int idx = blockIdx.x * blockDim.x + threadIdx.x;
    if (idx >= BNTOT) return;
    float u = g_P[idx]              + g_P[3 * BNTOT + idx]     + g_P[6 * BNTOT + idx];
    float v = g_P[BNTOT + idx]      + g_P[4 * BNTOT + idx]     + g_P[7 * BNTOT + idx];
    float w = g_P[2 * BNTOT + idx]  + g_P[5 * BNTOT + idx]     + g_P[8 * BNTOT + idx];
    float a = tanhf(u);
    float ssq = 1.f - a * a;
    split2(a,                           &oh[idx],             &ol[idx]);
    split2(ssq * v,                     &oh[BNTOT + idx],     &ol[BNTOT + idx]);
    split2(ssq * (w - 2.f * a * v * v), &oh[2 * BNTOT + idx], &ol[2 * BNTOT + idx]);
}

// combine out-GEMM value stream, write d_out stream 0, emit sin/cos hi/lo
__global__ void sincos_kernel(float* __restrict__ out)
{
    int idx = blockIdx.x * blockDim.x + threadIdx.x;
    if (idx >= BNTOT) return;
    float o = g_P[idx] + g_P[3 * BNTOT + idx] + g_P[6 * BNTOT + idx];
    out[idx] = o;
    float s, c;
    sincosf(o, &s, &c);
    split2(s, &g_SCh[idx],         &g_SCl[idx]);
    split2(c, &g_SCh[BNTOT + idx], &g_SCl[BNTOT + idx]);
}

// combine out_t/out_tt partials + conn partials -> d_out streams 1,2
__global__ void final_kernel(float* __restrict__ out, const float* __restrict__ lm,
                             const float* __restrict__ ld, const float* __restrict__ p)
{
    int idx = blockIdx.x * blockDim.x + threadIdx.x;
    if (idx >= BNTOT) return;
    int col = idx & (NB - 1);
    float ot  = g_P[BNTOT + idx]     + g_P[4 * BNTOT + idx] + g_P[7 * BNTOT + idx];
    float ott = g_P[2 * BNTOT + idx] + g_P[5 * BNTOT + idx] + g_P[8 * BNTOT + idx];
    float ssS = g_SSp[idx]           + g_SSp[2 * BNTOT + idx] + g_SSp[4 * BNTOT + idx];
    float ssC = g_SSp[BNTOT + idx]   + g_SSp[3 * BNTOT + idx] + g_SSp[5 * BNTOT + idx];
    float s, c;
    sincosf(out[idx], &s, &c);
    float conn = s * ssC - c * ssS;
    out[BNTOT + idx]     = ot;
    out[2 * BNTOT + idx] = lm[col] * ott + ld[col] * ot + conn - p[idx];
}

// ---------------------------------------------------------------------------
// Launch
// ---------------------------------------------------------------------------
extern "C" void kernel_launch(void* const* d_in, const int* in_sizes, int n_in,
                              void* d_out, int out_size)
{
    const float* t    = (const float*)d_in[0];
    const float* p    = (const float*)d_in[1];
    const float* W0   = (const float*)d_in[2];
    const float* b0   = (const float*)d_in[3];
    const float* W1   = (const float*)d_in[4];
    const float* b1   = (const float*)d_in[5];
    const float* W2   = (const float*)d_in[6];
    const float* b2   = (const float*)d_in[7];
    const float* Wout = (const float*)d_in[8];
    const float* bout = (const float*)d_in[9];
    const float* lm   = (const float*)d_in[10];
    const float* ld   = (const float*)d_in[11];
    const float* lb   = (const float*)d_in[12];
    const float* pl   = (const float*)d_in[13];
    const float* pu   = (const float*)d_in[14];
    float* out = (float*)d_out;

    cudaFuncSetAttribute(hmma_gemm_z, cudaFuncAttributeMaxDynamicSharedMemorySize, 3 * STG_BYTES);
    const int GSM = 3 * STG_BYTES;

    __nv_bfloat16 *pXh,*pXl,*pW0h,*pW0l,*pW1h,*pW1l,*pW2h,*pW2l,*pWoh,*pWol,*pLbh,*pLbl;
    __nv_bfloat16 *pAh,*pAl,*pBh,*pBl,*pSCh,*pSCl;
    float *pP,*pSSp;
    cudaGetSymbolAddress((void**)&pXh, g_Xh);   cudaGetSymbolAddress((void**)&pXl, g_Xl);
    cudaGetSymbolAddress((void**)&pW0h, g_W0Th);cudaGetSymbolAddress((void**)&pW0l, g_W0Tl);
    cudaGetSymbolAddress((void**)&pW1h, g_W1Th);cudaGetSymbolAddress((void**)&pW1l, g_W1Tl);
    cudaGetSymbolAddress((void**)&pW2h, g_W2Th);cudaGetSymbolAddress((void**)&pW2l, g_W2Tl);
    cudaGetSymbolAddress((void**)&pWoh, g_WoTh);cudaGetSymbolAddress((void**)&pWol, g_WoTl);
    cudaGetSymbolAddress((void**)&pLbh, g_Lbh); cudaGetSymbolAddress((void**)&pLbl, g_Lbl);
    cudaGetSymbolAddress((void**)&pAh, g_Ah);   cudaGetSymbolAddress((void**)&pAl, g_Al);
    cudaGetSymbolAddress((void**)&pBh, g_Bh);   cudaGetSymbolAddress((void**)&pBl, g_Bl);
    cudaGetSymbolAddress((void**)&pSCh, g_SCh); cudaGetSymbolAddress((void**)&pSCl, g_SCl);
    cudaGetSymbolAddress((void**)&pP, g_P);     cudaGetSymbolAddress((void**)&pSSp, g_SSp);

    const int EW = 256;
    // prep
    build_x_kernel<<<(BATCH * KP + EW - 1) / EW, EW>>>(t, p, pl, pu);
    prep_all<<<dim3(KP / 32, HD / 32, 5), dim3(32, 8)>>>(W0, W1, W2, Wout, lb);

    // layer 0: [1024,576] x [512,576]^T + b0  (3 segment partials)
    hmma_gemm_z<<<dim3(HD / 128, BATCH / 128, 3), 256, GSM>>>(pXh, pXl, pW0h, pW0l, pP, BATCH, HD, KP, b0, BATCH);
    act0_kernel<<<(BNTOT + EW - 1) / EW, EW>>>(W0);

    // layer 1: [3072,512] x W1^T
    hmma_gemm_z<<<dim3(HD / 128, 3 * BATCH / 128, 3), 256, GSM>>>(pAh, pAl, pW1h, pW1l, pP, 3 * BATCH, HD, HD, b1, BATCH);
    act12_kernel<<<(BNTOT + EW - 1) / EW, EW>>>(pBh, pBl);

    // layer 2
    hmma_gemm_z<<<dim3(HD / 128, 3 * BATCH / 128, 3), 256, GSM>>>(pBh, pBl, pW2h, pW2l, pP, 3 * BATCH, HD, HD, b2, BATCH);
    act12_kernel<<<(BNTOT + EW - 1) / EW, EW>>>(pAh, pAl);

    // output layer -> partials in g_P
    hmma_gemm_z<<<dim3(NB / 128, 3 * BATCH / 128, 3), 256, GSM>>>(pAh, pAl, pWoh, pWol, pP, 3 * BATCH, NB, HD, bout, BATCH);

    // combine value stream -> d_out stream0, sin/cos split
    sincos_kernel<<<(BNTOT + EW - 1) / EW, EW>>>(out);

    // connectivity: [sin;cos] [2048,512] x lambda_b^T -> partials in g_SSp
    hmma_gemm_z<<<dim3(NB / 128, 2 * BATCH / 128, 3), 256, GSM>>>(pSCh, pSCl, pLbh, pLbl, pSSp, 2 * BATCH, NB, NB, nullptr, 0);

    // combine streams 1,2 + physics -> d_out
    final_kernel<<<(BNTOT + EW - 1) / EW, EW>>>(out, lm, ld, p);
}

// round 7
// speedup vs baseline: 2.3512x; 1.0190x over previous
#include <cuda_runtime.h>
#include <cuda_bf16.h>
#include <math.h>
#include <stdint.h>

// Problem dims
#define BATCH 1024
#define NB    512
#define HD    512
#define KP    576            // padded input dim (1+512 -> 576 = 9*64)
#define BNTOT (BATCH*NB)     // 524288

// ---------------------------------------------------------------------------
// Scratch (device globals)
// ---------------------------------------------------------------------------
__device__ __nv_bfloat16 g_Xh[BATCH*KP],  g_Xl[BATCH*KP];
__device__ __nv_bfloat16 g_W0Th[HD*KP],   g_W0Tl[HD*KP];     // W0^T padded [512 x 576]
__device__ __nv_bfloat16 g_W1Th[HD*HD],   g_W1Tl[HD*HD];
__device__ __nv_bfloat16 g_W2Th[HD*HD],   g_W2Tl[HD*HD];
__device__ __nv_bfloat16 g_WoTh[HD*NB],   g_WoTl[HD*NB];     // Wout^T [512 x 512]
__device__ __nv_bfloat16 g_Lbh[NB*NB],    g_Lbl[NB*NB];      // lambda_b rows
__device__ __nv_bfloat16 g_Ah[3*BNTOT],   g_Al[3*BNTOT];     // activations ping
__device__ __nv_bfloat16 g_Bh[3*BNTOT],   g_Bl[3*BNTOT];     // activations pong
__device__ __nv_bfloat16 g_SCh[2*BNTOT],  g_SCl[2*BNTOT];    // [sin ; cos] hi/lo
__device__ float g_P  [3*3*BNTOT];   // GEMM partials: segment s at offset s*M*N
__device__ float g_SSp[3*2*BNTOT];   // conn GEMM partials

__device__ __forceinline__ void split2(float x, __nv_bfloat16* h, __nv_bfloat16* l) {
    __nv_bfloat16 hi = __float2bfloat16_rn(x);
    *h = hi;
    *l = __float2bfloat16_rn(x - __bfloat162float(hi));
}

__device__ __forceinline__ uint32_t smem_u32(const void* p) {
    uint32_t a;
    asm("{ .reg .u64 t; cvta.to.shared.u64 t, %1; cvt.u32.u64 %0, t; }" : "=r"(a) : "l"(p));
    return a;
}

__device__ __forceinline__ void mma_bf16(float* d, const uint32_t* a, uint32_t b0, uint32_t b1) {
    asm volatile(
        "mma.sync.aligned.m16n8k16.row.col.f32.bf16.bf16.f32 "
        "{%0,%1,%2,%3},{%4,%5,%6,%7},{%8,%9},{%0,%1,%2,%3};"
        : "+f"(d[0]), "+f"(d[1]), "+f"(d[2]), "+f"(d[3])
        : "r"(a[0]), "r"(a[1]), "r"(a[2]), "r"(a[3]), "r"(b0), "r"(b1));
}

// exact tanh identity; only MUFU error. Saturates correctly at +/-inf.
__device__ __forceinline__ float tanh_fast(float u) {
    float e = __expf(2.f * u);
    return 1.f - 2.f / (e + 1.f);
}

// ---- 8-wide vector helpers --------------------------------------------------
__device__ __forceinline__ void ld8(const float* p, float r[8]) {
    float4 a = *(const float4*)p, b = *(const float4*)(p + 4);
    r[0]=a.x; r[1]=a.y; r[2]=a.z; r[3]=a.w; r[4]=b.x; r[5]=b.y; r[6]=b.z; r[7]=b.w;
}
__device__ __forceinline__ void acc8(const float* p, float r[8]) {
    float4 a = *(const float4*)p, b = *(const float4*)(p + 4);
    r[0]+=a.x; r[1]+=a.y; r[2]+=a.z; r[3]+=a.w; r[4]+=b.x; r[5]+=b.y; r[6]+=b.z; r[7]+=b.w;
}
__device__ __forceinline__ void st8f(float* p, const float r[8]) {
    *(float4*)p       = make_float4(r[0], r[1], r[2], r[3]);
    *(float4*)(p + 4) = make_float4(r[4], r[5], r[6], r[7]);
}
// split 8 fp32 -> hi/lo bf16 arrays (two uint4 stores)
__device__ __forceinline__ void split8(const float r[8], __nv_bfloat16* ph, __nv_bfloat16* pl) {
    uint32_t h[4], l[4];
#pragma unroll
    for (int q = 0; q < 4; q++) {
        float x0 = r[2*q], x1 = r[2*q+1];
        __nv_bfloat162 hh = __floats2bfloat162_rn(x0, x1);
        float f0 = __bfloat162float(hh.x), f1 = __bfloat162float(hh.y);
        __nv_bfloat162 ll = __floats2bfloat162_rn(x0 - f0, x1 - f1);
        h[q] = *(uint32_t*)&hh;
        l[q] = *(uint32_t*)&ll;
    }
    *(uint4*)ph = make_uint4(h[0], h[1], h[2], h[3]);
    *(uint4*)pl = make_uint4(l[0], l[1], l[2], l[3]);
}

// ---------------------------------------------------------------------------
// HMMA split-bf16 GEMM, z-split over compensation segments.
// blockIdx.z = s in {0,1,2}: s=0: Ah*Bh (+bias), s=1: Ah*Bl, s=2: Al*Bh.
// CTA tile 128x128, Kc=64 (128B rows, XOR-8 swizzle), 3-stage cp.async
// pipeline (96KB dynamic smem), 2 CTAs/SM.
// ---------------------------------------------------------------------------
#define STG_BYTES 32768   // 16KB A + 16KB B per stage

__global__ void __launch_bounds__(256, 2)
hmma_gemm_z(const __nv_bfloat16* __restrict__ Ah, const __nv_bfloat16* __restrict__ Al,
            const __nv_bfloat16* __restrict__ Bh, const __nv_bfloat16* __restrict__ Bl,
            float* __restrict__ Cpart, int M, int N, int K,
            const float* __restrict__ bias, int bias_rows)
{
    extern __shared__ __align__(1024) char smem[];
    const uint32_t sb = smem_u32(smem);
    const int tid = threadIdx.x;
    const int lane = tid & 31;
    const int wid = tid >> 5;
    const int wm = wid & 3;          // M direction (4 x 32 = 128)
    const int wn = wid >> 2;         // N direction (2 x 64 = 128)
    const int m0 = blockIdx.y * 128;
    const int n0 = blockIdx.x * 128;
    const int s  = blockIdx.z;
    const int ncK = K >> 6;

    const __nv_bfloat16* __restrict__ Ap = (s < 2) ? Ah : Al;
    const __nv_bfloat16* __restrict__ Bp = (s == 1) ? Bl : Bh;
    float* __restrict__ C = Cpart + (size_t)s * M * N;
    const float* bp = (s == 0) ? bias : nullptr;

    float acc[2][8][4];
#pragma unroll
    for (int i = 0; i < 2; i++)
#pragma unroll
        for (int j = 0; j < 8; j++)
#pragma unroll
            for (int q = 0; q < 4; q++) acc[i][j][q] = 0.f;

    auto load_stage = [&](int kk, int stg) {
        const int kbase = kk << 6;
        const uint32_t abase = sb + stg * STG_BYTES;
        const uint32_t bbase = abase + 16384;
#pragma unroll
        for (int pass = 0; pass < 4; pass++) {
            int idx = pass * 256 + tid;
            int row = idx >> 3, ch = idx & 7;
            uint32_t sa = abase + row * 128 + ((ch ^ (row & 7)) << 4);
            const void* ga = Ap + (size_t)(m0 + row) * K + kbase + ch * 8;
            asm volatile("cp.async.cg.shared.global [%0], [%1], 16;" :: "r"(sa), "l"(ga));
        }
#pragma unroll
        for (int pass = 0; pass < 4; pass++) {
            int idx = pass * 256 + tid;
            int row = idx >> 3, ch = idx & 7;
            uint32_t sa = bbase + row * 128 + ((ch ^ (row & 7)) << 4);
            const void* ga = Bp + (size_t)(n0 + row) * K + kbase + ch * 8;
            asm volatile("cp.async.cg.shared.global [%0], [%1], 16;" :: "r"(sa), "l"(ga));
        }
    };

    // prologue: 2 stages in flight
    load_stage(0, 0);
    asm volatile("cp.async.commit_group;" ::: "memory");
    load_stage(1, 1);
    asm volatile("cp.async.commit_group;" ::: "memory");

    int cbuf = 0, nbuf = 2;
    for (int c = 0; c < ncK; c++) {
        asm volatile("cp.async.wait_group 1;" ::: "memory");
        __syncthreads();
        if (c + 2 < ncK) load_stage(c + 2, nbuf);
        asm volatile("cp.async.commit_group;" ::: "memory");

        const uint32_t abase = sb + cbuf * STG_BYTES;
        const uint32_t bbase = abase + 16384;

#pragma unroll
        for (int kb = 0; kb < 4; kb++) {
            uint32_t a[2][4];
#pragma unroll
            for (int i = 0; i < 2; i++) {
                int row = wm * 32 + i * 16 + (lane & 15);
                int ch  = kb * 2 + (lane >> 4);
                uint32_t ad = abase + row * 128 + ((ch ^ (row & 7)) << 4);
                asm volatile("ldmatrix.sync.aligned.m8n8.x4.shared.b16 {%0,%1,%2,%3}, [%4];"
                             : "=r"(a[i][0]), "=r"(a[i][1]), "=r"(a[i][2]), "=r"(a[i][3])
                             : "r"(ad));
            }
#pragma unroll
            for (int j = 0; j < 4; j++) {
                uint32_t b[4];
                int rn  = (lane & 7) + ((lane >> 4) << 3);
                int row = wn * 64 + j * 16 + rn;
                int ch  = kb * 2 + ((lane >> 3) & 1);
                uint32_t bd = bbase + row * 128 + ((ch ^ (row & 7)) << 4);
                asm volatile("ldmatrix.sync.aligned.m8n8.x4.shared.b16 {%0,%1,%2,%3}, [%4];"
                             : "=r"(b[0]), "=r"(b[1]), "=r"(b[2]), "=r"(b[3])
                             : "r"(bd));
#pragma unroll
                for (int i = 0; i < 2; i++) {
                    mma_bf16(acc[i][2 * j],     a[i], b[0], b[1]);
                    mma_bf16(acc[i][2 * j + 1], a[i], b[2], b[3]);
                }
            }
        }
        cbuf = (cbuf == 2) ? 0 : cbuf + 1;
        nbuf = (nbuf == 2) ? 0 : nbuf + 1;
    }

    // epilogue
    const int gr  = lane >> 2;           // row within 8
    const int cp2 = (lane & 3) * 2;      // col pair
#pragma unroll
    for (int i = 0; i < 2; i++) {
#pragma unroll
        for (int j8 = 0; j8 < 8; j8++) {
            int col = n0 + wn * 64 + j8 * 8 + cp2;
            int r0  = m0 + wm * 32 + i * 16 + gr;
            float bx = 0.f, by = 0.f;
            if (bp) { bx = bp[col]; by = bp[col + 1]; }
#pragma unroll
            for (int rr = 0; rr < 2; rr++) {
                int row = r0 + rr * 8;
                float2 v;
                v.x = acc[i][j8][2 * rr + 0];
                v.y = acc[i][j8][2 * rr + 1];
                if (bp && row < bias_rows) { v.x += bx; v.y += by; }
                *reinterpret_cast<float2*>(&C[(size_t)row * N + col]) = v;
            }
        }
    }
}

// ---------------------------------------------------------------------------
// Fused prep: z<4 -> tiled transpose+split of W0/W1/W2/Wout; z==4 -> lambda_b
// ---------------------------------------------------------------------------
__global__ void prep_all(const float* __restrict__ W0, const float* __restrict__ W1,
                         const float* __restrict__ W2, const float* __restrict__ Wo,
                         const float* __restrict__ lb)
{
    const int tx = threadIdx.x, ty = threadIdx.y;
    const int kb = blockIdx.x * 32, nb = blockIdx.y * 32;
    const int z = blockIdx.z;

    if (z == 4) {  // lambda_b straight split
        if (kb >= NB) return;
#pragma unroll
        for (int i = 0; i < 32; i += 8) {
            size_t o = (size_t)(nb + ty + i) * NB + kb + tx;
            split2(lb[o], &g_Lbh[o], &g_Lbl[o]);
        }
        return;
    }

    const float* W; __nv_bfloat16 *oh, *ol; int Kin, Kout;
    if (z == 0)      { W = W0; oh = g_W0Th; ol = g_W0Tl; Kin = NB + 1; Kout = KP; }
    else if (z == 1) { W = W1; oh = g_W1Th; ol = g_W1Tl; Kin = HD;     Kout = HD; }
    else if (z == 2) { W = W2; oh = g_W2Th; ol = g_W2Tl; Kin = HD;     Kout = HD; }
    else             { W = Wo; oh = g_WoTh; ol = g_WoTl; Kin = HD;     Kout = HD; }
    if (kb >= Kout) return;

    __shared__ float tile[32][33];
#pragma unroll
    for (int i = 0; i < 32; i += 8) {
        int k = kb + ty + i;
        tile[ty + i][tx] = (k < Kin) ? W[(size_t)k * HD + nb + tx] : 0.f;
    }
    __syncthreads();
#pragma unroll
    for (int i = 0; i < 32; i += 8) {
        int n = nb + ty + i;
        size_t o = (size_t)n * Kout + kb + tx;
        split2(tile[tx][ty + i], &oh[o], &ol[o]);
    }
}

// ---------------------------------------------------------------------------
// Elementwise kernels (8 elements per thread)
// ---------------------------------------------------------------------------
__global__ void build_x_kernel(const float* __restrict__ t, const float* __restrict__ p,
                               const float* __restrict__ pl, const float* __restrict__ pu)
{
    int idx = blockIdx.x * blockDim.x + threadIdx.x;
    if (idx >= BATCH * KP) return;
    int row = idx / KP, col = idx - row * KP;
    float v;
    if (col == 0) v = 0.2f * t[row] - 1.0f;
    else if (col <= NB) {
        int j = col - 1;
        float lo = pl[j], hi = pu[j];
        v = (hi == lo) ? 0.f : (2.f * (p[row * NB + j] - lo) / (hi - lo) - 1.f);
    } else v = 0.f;
    split2(v, &g_Xh[idx], &g_Xl[idx]);
}

// layer0: partials at {0,1,2}*BNTOT (per-segment size BNTOT)
__global__ void act0_kernel(const float* __restrict__ W0)
{
    int i = (blockIdx.x * blockDim.x + threadIdx.x) * 8;
    if (i >= BNTOT) return;
    int col = i & (HD - 1);
    float u[8], w0[8];
    ld8(g_P + i, u); acc8(g_P + BNTOT + i, u); acc8(g_P + 2 * BNTOT + i, u);
    ld8(W0 + col, w0);                           // W0 row 0
    float a[8], d1[8], d2[8];
#pragma unroll
    for (int q = 0; q < 8; q++) {
        float av = tanh_fast(u[q]);
        float ssq = 1.f - av * av;
        float gth = 0.2f * w0[q];
        a[q]  = av;
        d1[q] = ssq * gth;
        d2[q] = -2.f * av * ssq * gth * gth;
    }
    split8(a,  g_Ah + i,             g_Al + i);
    split8(d1, g_Ah + BNTOT + i,     g_Al + BNTOT + i);
    split8(d2, g_Ah + 2 * BNTOT + i, g_Al + 2 * BNTOT + i);
}

// layers 1/2: per-segment size 3*BNTOT; stream t at t*BNTOT
__global__ void act12_kernel(__nv_bfloat16* __restrict__ oh, __nv_bfloat16* __restrict__ ol)
{
    int i = (blockIdx.x * blockDim.x + threadIdx.x) * 8;
    if (i >= BNTOT) return;
    float u[8], v[8], w[8];
    ld8(g_P + i, u);              acc8(g_P + 3 * BNTOT + i, u); acc8(g_P + 6 * BNTOT + i, u);
    ld8(g_P + BNTOT + i, v);      acc8(g_P + 4 * BNTOT + i, v); acc8(g_P + 7 * BNTOT + i, v);
    ld8(g_P + 2 * BNTOT + i, w);  acc8(g_P + 5 * BNTOT + i, w); acc8(g_P + 8 * BNTOT + i, w);
    float a[8], d1[8], d2[8];
#pragma unroll
    for (int q = 0; q < 8; q++) {
        float av = tanh_fast(u[q]);
        float ssq = 1.f - av * av;
        a[q]  = av;
        d1[q] = ssq * v[q];
        d2[q] = ssq * (w[q] - 2.f * av * v[q] * v[q]);
    }
    split8(a,  oh + i,             ol + i);
    split8(d1, oh + BNTOT + i,     ol + BNTOT + i);
    split8(d2, oh + 2 * BNTOT + i, ol + 2 * BNTOT + i);
}

// combine out value stream -> d_out stream 0, emit sin/cos hi/lo
__global__ void sincos_kernel(float* __restrict__ out)
{
    int i = (blockIdx.x * blockDim.x + threadIdx.x) * 8;
    if (i >= BNTOT) return;
    float o[8];
    ld8(g_P + i, o); acc8(g_P + 3 * BNTOT + i, o); acc8(g_P + 6 * BNTOT + i, o);
    st8f(out + i, o);
    float sv[8], cv[8];
#pragma unroll
    for (int q = 0; q < 8; q++) __sincosf(o[q], &sv[q], &cv[q]);
    split8(sv, g_SCh + i,         g_SCl + i);
    split8(cv, g_SCh + BNTOT + i, g_SCl + BNTOT + i);
}

// combine streams 1,2 + conn partials + physics -> d_out
__global__ void final_kernel(float* __restrict__ out, const float* __restrict__ lm,
                             const float* __restrict__ ld, const float* __restrict__ p)
{
    int i = (blockIdx.x * blockDim.x + threadIdx.x) * 8;
    if (i >= BNTOT) return;
    int col = i & (NB - 1);
    float ot[8], ott[8], ssS[8], ssC[8], ov[8], pv[8], lmv[8], ldv[8];
    ld8(g_P + BNTOT + i, ot);       acc8(g_P + 4 * BNTOT + i, ot);  acc8(g_P + 7 * BNTOT + i, ot);
    ld8(g_P + 2 * BNTOT + i, ott);  acc8(g_P + 5 * BNTOT + i, ott); acc8(g_P + 8 * BNTOT + i, ott);
    ld8(g_SSp + i, ssS);            acc8(g_SSp + 2 * BNTOT + i, ssS); acc8(g_SSp + 4 * BNTOT + i, ssS);
    ld8(g_SSp + BNTOT + i, ssC);    acc8(g_SSp + 3 * BNTOT + i, ssC); acc8(g_SSp + 5 * BNTOT + i, ssC);
    ld8(out + i, ov);
    ld8(p + i, pv);
    ld8(lm + col, lmv);
    ld8(ld + col, ldv);
    float r1[8], r2[8];
#pragma unroll
    for (int q = 0; q < 8; q++) {
        float s, c;
        __sincosf(ov[q], &s, &c);
        float conn = s * ssC[q] - c * ssS[q];
        r1[q] = ot[q];
        r2[q] = lmv[q] * ott[q] + ldv[q] * ot[q] + conn - pv[q];
    }
    st8f(out + BNTOT + i, r1);
    st8f(out + 2 * BNTOT + i, r2);
}

// ---------------------------------------------------------------------------
// Launch
// ---------------------------------------------------------------------------
extern "C" void kernel_launch(void* const* d_in, const int* in_sizes, int n_in,
                              void* d_out, int out_size)
{
    const float* t    = (const float*)d_in[0];
    const float* p    = (const float*)d_in[1];
    const float* W0   = (const float*)d_in[2];
    const float* b0   = (const float*)d_in[3];
    const float* W1   = (const float*)d_in[4];
    const float* b1   = (const float*)d_in[5];
    const float* W2   = (const float*)d_in[6];
    const float* b2   = (const float*)d_in[7];
    const float* Wout = (const float*)d_in[8];
    const float* bout = (const float*)d_in[9];
    const float* lm   = (const float*)d_in[10];
    const float* ld   = (const float*)d_in[11];
    const float* lb   = (const float*)d_in[12];
    const float* pl   = (const float*)d_in[13];
    const float* pu   = (const float*)d_in[14];
    float* out = (float*)d_out;

    cudaFuncSetAttribute(hmma_gemm_z, cudaFuncAttributeMaxDynamicSharedMemorySize, 3 * STG_BYTES);
    const int GSM = 3 * STG_BYTES;

    __nv_bfloat16 *pXh,*pXl,*pW0h,*pW0l,*pW1h,*pW1l,*pW2h,*pW2l,*pWoh,*pWol,*pLbh,*pLbl;
    __nv_bfloat16 *pAh,*pAl,*pBh,*pBl,*pSCh,*pSCl;
    float *pP,*pSSp;
    cudaGetSymbolAddress((void**)&pXh, g_Xh);   cudaGetSymbolAddress((void**)&pXl, g_Xl);
    cudaGetSymbolAddress((void**)&pW0h, g_W0Th);cudaGetSymbolAddress((void**)&pW0l, g_W0Tl);
    cudaGetSymbolAddress((void**)&pW1h, g_W1Th);cudaGetSymbolAddress((void**)&pW1l, g_W1Tl);
    cudaGetSymbolAddress((void**)&pW2h, g_W2Th);cudaGetSymbolAddress((void**)&pW2l, g_W2Tl);
    cudaGetSymbolAddress((void**)&pWoh, g_WoTh);cudaGetSymbolAddress((void**)&pWol, g_WoTl);
    cudaGetSymbolAddress((void**)&pLbh, g_Lbh); cudaGetSymbolAddress((void**)&pLbl, g_Lbl);
    cudaGetSymbolAddress((void**)&pAh, g_Ah);   cudaGetSymbolAddress((void**)&pAl, g_Al);
    cudaGetSymbolAddress((void**)&pBh, g_Bh);   cudaGetSymbolAddress((void**)&pBl, g_Bl);
    cudaGetSymbolAddress((void**)&pSCh, g_SCh); cudaGetSymbolAddress((void**)&pSCl, g_SCl);
    cudaGetSymbolAddress((void**)&pP, g_P);     cudaGetSymbolAddress((void**)&pSSp, g_SSp);

    const int EW = 256;
    const int VG = BNTOT / (EW * 8);   // 256 blocks for 8-wide kernels

    // prep
    build_x_kernel<<<(BATCH * KP + EW - 1) / EW, EW>>>(t, p, pl, pu);
    prep_all<<<dim3(KP / 32, HD / 32, 5), dim3(32, 8)>>>(W0, W1, W2, Wout, lb);

    // layer 0: [1024,576] x [512,576]^T + b0  (3 segment partials)
    hmma_gemm_z<<<dim3(HD / 128, BATCH / 128, 3), 256, GSM>>>(pXh, pXl, pW0h, pW0l, pP, BATCH, HD, KP, b0, BATCH);
    act0_kernel<<<VG, EW>>>(W0);

    // layer 1: [3072,512] x W1^T
    hmma_gemm_z<<<dim3(HD / 128, 3 * BATCH / 128, 3), 256, GSM>>>(pAh, pAl, pW1h, pW1l, pP, 3 * BATCH, HD, HD, b1, BATCH);
    act12_kernel<<<VG, EW>>>(pBh, pBl);

    // layer 2
    hmma_gemm_z<<<dim3(HD / 128, 3 * BATCH / 128, 3), 256, GSM>>>(pBh, pBl, pW2h, pW2l, pP, 3 * BATCH, HD, HD, b2, BATCH);
    act12_kernel<<<VG, EW>>>(pAh, pAl);

    // output layer -> partials in g_P
    hmma_gemm_z<<<dim3(NB / 128, 3 * BATCH / 128, 3), 256, GSM>>>(pAh, pAl, pWoh, pWol, pP, 3 * BATCH, NB, HD, bout, BATCH);

    // combine value stream -> d_out stream0, sin/cos split
    sincos_kernel<<<VG, EW>>>(out);

    // connectivity: [sin;cos] [2048,512] x lambda_b^T -> partials in g_SSp
    hmma_gemm_z<<<dim3(NB / 128, 2 * BATCH / 128, 3), 256, GSM>>>(pSCh, pSCl, pLbh, pLbl, pSSp, 2 * BATCH, NB, NB, nullptr, 0);

    // combine streams 1,2 + physics -> d_out
    final_kernel<<<VG, EW>>>(out, lm, ld, p);
}

// round 9
// speedup vs baseline: 2.3974x; 1.0197x over previous
#include <cuda_runtime.h>
#include <cuda_bf16.h>
#include <math.h>
#include <stdint.h>

// Problem dims
#define BATCH 1024
#define NB    512
#define HD    512
#define KP    576            // padded input dim (1+512 -> 576 = 9*64)
#define BNTOT (BATCH*NB)     // 524288

// ---------------------------------------------------------------------------
// Scratch (device globals)
// ---------------------------------------------------------------------------
__device__ __nv_bfloat16 g_Xh[BATCH*KP],  g_Xl[BATCH*KP];
__device__ __nv_bfloat16 g_W0Th[HD*KP],   g_W0Tl[HD*KP];     // W0^T padded [512 x 576]
__device__ __nv_bfloat16 g_W1Th[HD*HD],   g_W1Tl[HD*HD];
__device__ __nv_bfloat16 g_W2Th[HD*HD],   g_W2Tl[HD*HD];
__device__ __nv_bfloat16 g_WoTh[HD*NB],   g_WoTl[HD*NB];     // Wout^T [512 x 512]
__device__ __nv_bfloat16 g_Lbh[NB*NB],    g_Lbl[NB*NB];      // lambda_b rows
__device__ __nv_bfloat16 g_Ah[3*BNTOT],   g_Al[3*BNTOT];     // activations ping
__device__ __nv_bfloat16 g_Bh[3*BNTOT],   g_Bl[3*BNTOT];     // activations pong
__device__ __nv_bfloat16 g_SCh[2*BNTOT],  g_SCl[2*BNTOT];    // [sin ; cos] hi/lo
__device__ float g_P  [3*3*BNTOT];   // GEMM partials: segment s at offset s*M*N
__device__ float g_SSp[3*2*BNTOT];   // conn GEMM partials

__device__ __forceinline__ void split2(float x, __nv_bfloat16* h, __nv_bfloat16* l) {
    __nv_bfloat16 hi = __float2bfloat16_rn(x);
    *h = hi;
    *l = __float2bfloat16_rn(x - __bfloat162float(hi));
}

__device__ __forceinline__ uint32_t smem_u32(const void* p) {
    uint32_t a;
    asm("{ .reg .u64 t; cvta.to.shared.u64 t, %1; cvt.u32.u64 %0, t; }" : "=r"(a) : "l"(p));
    return a;
}

__device__ __forceinline__ void mma_bf16(float* d, const uint32_t* a, uint32_t b0, uint32_t b1) {
    asm volatile(
        "mma.sync.aligned.m16n8k16.row.col.f32.bf16.bf16.f32 "
        "{%0,%1,%2,%3},{%4,%5,%6,%7},{%8,%9},{%0,%1,%2,%3};"
        : "+f"(d[0]), "+f"(d[1]), "+f"(d[2]), "+f"(d[3])
        : "r"(a[0]), "r"(a[1]), "r"(a[2]), "r"(a[3]), "r"(b0), "r"(b1));
}

// 1-MUFU tanh: e = exp(-2|u|) (EX2), then (1-e)/(1+e) with FFMA-only
// reciprocal of d=1+e on (1,2]: seed r0 = 24/17 - 8/17*d (max rel err 1/17,
// positive over the whole interval), 3 Newton steps -> rel err ~1.4e-10.
__device__ __forceinline__ float tanh_fast(float u) {
    float au = fabsf(u);
    float e = __expf(-2.f * au);                        // 1 MUFU
    float d = 1.f + e;
    float r = __fmaf_rn(-0.47058824f, d, 1.41176471f);  // 24/17 - 8/17*d
    r = r * (2.f - d * r);
    r = r * (2.f - d * r);
    r = r * (2.f - d * r);
    float t = (1.f - e) * r;
    return copysignf(t, u);
}

// ---- 8-wide vector helpers --------------------------------------------------
__device__ __forceinline__ void ld8(const float* p, float r[8]) {
    float4 a = *(const float4*)p, b = *(const float4*)(p + 4);
    r[0]=a.x; r[1]=a.y; r[2]=a.z; r[3]=a.w; r[4]=b.x; r[5]=b.y; r[6]=b.z; r[7]=b.w;
}
__device__ __forceinline__ void acc8(const float* p, float r[8]) {
    float4 a = *(const float4*)p, b = *(const float4*)(p + 4);
    r[0]+=a.x; r[1]+=a.y; r[2]+=a.z; r[3]+=a.w; r[4]+=b.x; r[5]+=b.y; r[6]+=b.z; r[7]+=b.w;
}
__device__ __forceinline__ void st8f(float* p, const float r[8]) {
    *(float4*)p       = make_float4(r[0], r[1], r[2], r[3]);
    *(float4*)(p + 4) = make_float4(r[4], r[5], r[6], r[7]);
}
// split 8 fp32 -> hi/lo bf16 arrays (two uint4 stores)
__device__ __forceinline__ void split8(const float r[8], __nv_bfloat16* ph, __nv_bfloat16* pl) {
    uint32_t h[4], l[4];
#pragma unroll
    for (int q = 0; q < 4; q++) {
        float x0 = r[2*q], x1 = r[2*q+1];
        __nv_bfloat162 hh = __floats2bfloat162_rn(x0, x1);
        float f0 = __bfloat162float(hh.x), f1 = __bfloat162float(hh.y);
        __nv_bfloat162 ll = __floats2bfloat162_rn(x0 - f0, x1 - f1);
        h[q] = *(uint32_t*)&hh;
        l[q] = *(uint32_t*)&ll;
    }
    *(uint4*)ph = make_uint4(h[0], h[1], h[2], h[3]);
    *(uint4*)pl = make_uint4(l[0], l[1], l[2], l[3]);
}
// read 8 (hi,lo) bf16 pairs -> fp32 sum
__device__ __forceinline__ void ld8bf2(const __nv_bfloat16* ph, const __nv_bfloat16* pl, float r[8]) {
    uint4 h = *(const uint4*)ph, l = *(const uint4*)pl;
    uint32_t hv[4] = {h.x, h.y, h.z, h.w};
    uint32_t lv[4] = {l.x, l.y, l.z, l.w};
#pragma unroll
    for (int q = 0; q < 4; q++) {
        __nv_bfloat162 hb = *(__nv_bfloat162*)&hv[q];
        __nv_bfloat162 lb = *(__nv_bfloat162*)&lv[q];
        r[2*q]   = __bfloat162float(hb.x) + __bfloat162float(lb.x);
        r[2*q+1] = __bfloat162float(hb.y) + __bfloat162float(lb.y);
    }
}

// ---------------------------------------------------------------------------
// HMMA split-bf16 GEMM, z-split over compensation segments.
// blockIdx.z = s in {0,1,2}: s=0: Ah*Bh (+bias), s=1: Ah*Bl, s=2: Al*Bh.
// CTA tile 128x128, Kc=64 (128B rows, XOR-8 swizzle), 3-stage cp.async
// pipeline (96KB dynamic smem), 2 CTAs/SM.
// ---------------------------------------------------------------------------
#define STG_BYTES 32768   // 16KB A + 16KB B per stage

__global__ void __launch_bounds__(256, 2)
hmma_gemm_z(const __nv_bfloat16* __restrict__ Ah, const __nv_bfloat16* __restrict__ Al,
            const __nv_bfloat16* __restrict__ Bh, const __nv_bfloat16* __restrict__ Bl,
            float* __restrict__ Cpart, int M, int N, int K,
            const float* __restrict__ bias, int bias_rows)
{
    extern __shared__ __align__(1024) char smem[];
    const uint32_t sb = smem_u32(smem);
    const int tid = threadIdx.x;
    const int lane = tid & 31;
    const int wid = tid >> 5;
    const int wm = wid & 3;          // M direction (4 x 32 = 128)
    const int wn = wid >> 2;         // N direction (2 x 64 = 128)
    const int m0 = blockIdx.y * 128;
    const int n0 = blockIdx.x * 128;
    const int s  = blockIdx.z;
    const int ncK = K >> 6;

    const __nv_bfloat16* __restrict__ Ap = (s < 2) ? Ah : Al;
    const __nv_bfloat16* __restrict__ Bp = (s == 1) ? Bl : Bh;
    float* __restrict__ C = Cpart + (size_t)s * M * N;
    const float* bp = (s == 0) ? bias : nullptr;

    float acc[2][8][4];
#pragma unroll
    for (int i = 0; i < 2; i++)
#pragma unroll
        for (int j = 0; j < 8; j++)
#pragma unroll
            for (int q = 0; q < 4; q++) acc[i][j][q] = 0.f;

    auto load_stage = [&](int kk, int stg) {
        const int kbase = kk << 6;
        const uint32_t abase = sb + stg * STG_BYTES;
        const uint32_t bbase = abase + 16384;
#pragma unroll
        for (int pass = 0; pass < 4; pass++) {
            int idx = pass * 256 + tid;
            int row = idx >> 3, ch = idx & 7;
            uint32_t sa = abase + row * 128 + ((ch ^ (row & 7)) << 4);
            const void* ga = Ap + (size_t)(m0 + row) * K + kbase + ch * 8;
            asm volatile("cp.async.cg.shared.global [%0], [%1], 16;" :: "r"(sa), "l"(ga));
        }
#pragma unroll
        for (int pass = 0; pass < 4; pass++) {
            int idx = pass * 256 + tid;
            int row = idx >> 3, ch = idx & 7;
            uint32_t sa = bbase + row * 128 + ((ch ^ (row & 7)) << 4);
            const void* ga = Bp + (size_t)(n0 + row) * K + kbase + ch * 8;
            asm volatile("cp.async.cg.shared.global [%0], [%1], 16;" :: "r"(sa), "l"(ga));
        }
    };

    // prologue: 2 stages in flight
    load_stage(0, 0);
    asm volatile("cp.async.commit_group;" ::: "memory");
    load_stage(1, 1);
    asm volatile("cp.async.commit_group;" ::: "memory");

    int cbuf = 0, nbuf = 2;
    for (int c = 0; c < ncK; c++) {
        asm volatile("cp.async.wait_group 1;" ::: "memory");
        __syncthreads();
        if (c + 2 < ncK) load_stage(c + 2, nbuf);
        asm volatile("cp.async.commit_group;" ::: "memory");

        const uint32_t abase = sb + cbuf * STG_BYTES;
        const uint32_t bbase = abase + 16384;

#pragma unroll
        for (int kb = 0; kb < 4; kb++) {
            uint32_t a[2][4];
#pragma unroll
            for (int i = 0; i < 2; i++) {
                int row = wm * 32 + i * 16 + (lane & 15);
                int ch  = kb * 2 + (lane >> 4);
                uint32_t ad = abase + row * 128 + ((ch ^ (row & 7)) << 4);
                asm volatile("ldmatrix.sync.aligned.m8n8.x4.shared.b16 {%0,%1,%2,%3}, [%4];"
                             : "=r"(a[i][0]), "=r"(a[i][1]), "=r"(a[i][2]), "=r"(a[i][3])
                             : "r"(ad));
            }
#pragma unroll
            for (int j = 0; j < 4; j++) {
                uint32_t b[4];
                int rn  = (lane & 7) + ((lane >> 4) << 3);
                int row = wn * 64 + j * 16 + rn;
                int ch  = kb * 2 + ((lane >> 3) & 1);
                uint32_t bd = bbase + row * 128 + ((ch ^ (row & 7)) << 4);
                asm volatile("ldmatrix.sync.aligned.m8n8.x4.shared.b16 {%0,%1,%2,%3}, [%4];"
                             : "=r"(b[0]), "=r"(b[1]), "=r"(b[2]), "=r"(b[3])
                             : "r"(bd));
#pragma unroll
                for (int i = 0; i < 2; i++) {
                    mma_bf16(acc[i][2 * j],     a[i], b[0], b[1]);
                    mma_bf16(acc[i][2 * j + 1], a[i], b[2], b[3]);
                }
            }
        }
        cbuf = (cbuf == 2) ? 0 : cbuf + 1;
        nbuf = (nbuf == 2) ? 0 : nbuf + 1;
    }

    // epilogue
    const int gr  = lane >> 2;           // row within 8
    const int cp2 = (lane & 3) * 2;      // col pair
#pragma unroll
    for (int i = 0; i < 2; i++) {
#pragma unroll
        for (int j8 = 0; j8 < 8; j8++) {
            int col = n0 + wn * 64 + j8 * 8 + cp2;
            int r0  = m0 + wm * 32 + i * 16 + gr;
            float bx = 0.f, by = 0.f;
            if (bp) { bx = bp[col]; by = bp[col + 1]; }
#pragma unroll
            for (int rr = 0; rr < 2; rr++) {
                int row = r0 + rr * 8;
                float2 v;
                v.x = acc[i][j8][2 * rr + 0];
                v.y = acc[i][j8][2 * rr + 1];
                if (bp && row < bias_rows) { v.x += bx; v.y += by; }
                *reinterpret_cast<float2*>(&C[(size_t)row * N + col]) = v;
            }
        }
    }
}

// ---------------------------------------------------------------------------
// Fused prep: z<4 -> tiled transpose+split of W0/W1/W2/Wout; z==4 -> lambda_b
// ---------------------------------------------------------------------------
__global__ void prep_all(const float* __restrict__ W0, const float* __restrict__ W1,
                         const float* __restrict__ W2, const float* __restrict__ Wo,
                         const float* __restrict__ lb)
{
    const int tx = threadIdx.x, ty = threadIdx.y;
    const int kb = blockIdx.x * 32, nb = blockIdx.y * 32;
    const int z = blockIdx.z;

    if (z == 4) {  // lambda_b straight split
        if (kb >= NB) return;
#pragma unroll
        for (int i = 0; i < 32; i += 8) {
            size_t o = (size_t)(nb + ty + i) * NB + kb + tx;
            split2(lb[o], &g_Lbh[o], &g_Lbl[o]);
        }
        return;
    }

    const float* W; __nv_bfloat16 *oh, *ol; int Kin, Kout;
    if (z == 0)      { W = W0; oh = g_W0Th; ol = g_W0Tl; Kin = NB + 1; Kout = KP; }
    else if (z == 1) { W = W1; oh = g_W1Th; ol = g_W1Tl; Kin = HD;     Kout = HD; }
    else if (z == 2) { W = W2; oh = g_W2Th; ol = g_W2Tl; Kin = HD;     Kout = HD; }
    else             { W = Wo; oh = g_WoTh; ol = g_WoTl; Kin = HD;     Kout = HD; }
    if (kb >= Kout) return;

    __shared__ float tile[32][33];
#pragma unroll
    for (int i = 0; i < 32; i += 8) {
        int k = kb + ty + i;
        tile[ty + i][tx] = (k < Kin) ? W[(size_t)k * HD + nb + tx] : 0.f;
    }
    __syncthreads();
#pragma unroll
    for (int i = 0; i < 32; i += 8) {
        int n = nb + ty + i;
        size_t o = (size_t)n * Kout + kb + tx;
        split2(tile[tx][ty + i], &oh[o], &ol[o]);
    }
}

// ---------------------------------------------------------------------------
// Elementwise kernels (8 elements per thread)
// ---------------------------------------------------------------------------
__global__ void build_x_kernel(const float* __restrict__ t, const float* __restrict__ p,
                               const float* __restrict__ pl, const float* __restrict__ pu)
{
    int idx = blockIdx.x * blockDim.x + threadIdx.x;
    if (idx >= BATCH * KP) return;
    int row = idx / KP, col = idx - row * KP;
    float v;
    if (col == 0) v = 0.2f * t[row] - 1.0f;
    else if (col <= NB) {
        int j = col - 1;
        float lo = pl[j], hi = pu[j];
        v = (hi == lo) ? 0.f : (__fdividef(2.f * (p[row * NB + j] - lo), hi - lo) - 1.f);
    } else v = 0.f;
    split2(v, &g_Xh[idx], &g_Xl[idx]);
}

// layer0: partials at {0,1,2}*BNTOT (per-segment size BNTOT)
__global__ void act0_kernel(const float* __restrict__ W0)
{
    int i = (blockIdx.x * blockDim.x + threadIdx.x) * 8;
    if (i >= BNTOT) return;
    int col = i & (HD - 1);
    float u[8], w0[8];
    ld8(g_P + i, u); acc8(g_P + BNTOT + i, u); acc8(g_P + 2 * BNTOT + i, u);
    ld8(W0 + col, w0);                           // W0 row 0
    float a[8], d1[8], d2[8];
#pragma unroll
    for (int q = 0; q < 8; q++) {
        float av = tanh_fast(u[q]);
        float ssq = 1.f - av * av;
        float gth = 0.2f * w0[q];
        a[q]  = av;
        d1[q] = ssq * gth;
        d2[q] = -2.f * av * ssq * gth * gth;
    }
    split8(a,  g_Ah + i,             g_Al + i);
    split8(d1, g_Ah + BNTOT + i,     g_Al + BNTOT + i);
    split8(d2, g_Ah + 2 * BNTOT + i, g_Al + 2 * BNTOT + i);
}

// layers 1/2: per-segment size 3*BNTOT; stream t at t*BNTOT
__global__ void act12_kernel(__nv_bfloat16* __restrict__ oh, __nv_bfloat16* __restrict__ ol)
{
    int i = (blockIdx.x * blockDim.x + threadIdx.x) * 8;
    if (i >= BNTOT) return;
    float u[8], v[8], w[8];
    ld8(g_P + i, u);              acc8(g_P + 3 * BNTOT + i, u); acc8(g_P + 6 * BNTOT + i, u);
    ld8(g_P + BNTOT + i, v);      acc8(g_P + 4 * BNTOT + i, v); acc8(g_P + 7 * BNTOT + i, v);
    ld8(g_P + 2 * BNTOT + i, w);  acc8(g_P + 5 * BNTOT + i, w); acc8(g_P + 8 * BNTOT + i, w);
    float a[8], d1[8], d2[8];
#pragma unroll
    for (int q = 0; q < 8; q++) {
        float av = tanh_fast(u[q]);
        float ssq = 1.f - av * av;
        a[q]  = av;
        d1[q] = ssq * v[q];
        d2[q] = ssq * (w[q] - 2.f * av * v[q] * v[q]);
    }
    split8(a,  oh + i,             ol + i);
    split8(d1, oh + BNTOT + i,     ol + BNTOT + i);
    split8(d2, oh + 2 * BNTOT + i, ol + 2 * BNTOT + i);
}

// combine out value stream -> d_out stream 0, emit sin/cos hi/lo
__global__ void sincos_kernel(float* __restrict__ out)
{
    int i = (blockIdx.x * blockDim.x + threadIdx.x) * 8;
    if (i >= BNTOT) return;
    float o[8];
    ld8(g_P + i, o); acc8(g_P + 3 * BNTOT + i, o); acc8(g_P + 6 * BNTOT + i, o);
    st8f(out + i, o);
    float sv[8], cv[8];
#pragma unroll
    for (int q = 0; q < 8; q++) __sincosf(o[q], &sv[q], &cv[q]);
    split8(sv, g_SCh + i,         g_SCl + i);
    split8(cv, g_SCh + BNTOT + i, g_SCl + BNTOT + i);
}

// combine streams 1,2 + conn partials + physics -> d_out
// s,c reconstructed from the stored hi/lo splits (no MUFU here)
__global__ void final_kernel(float* __restrict__ out, const float* __restrict__ lm,
                             const float* __restrict__ ld, const float* __restrict__ p)
{
    int i = (blockIdx.x * blockDim.x + threadIdx.x) * 8;
    if (i >= BNTOT) return;
    int col = i & (NB - 1);
    float ot[8], ott[8], ssS[8], ssC[8], pv[8], lmv[8], ldv[8], sv[8], cv[8];
    ld8(g_P + BNTOT + i, ot);       acc8(g_P + 4 * BNTOT + i, ot);  acc8(g_P + 7 * BNTOT + i, ot);
    ld8(g_P + 2 * BNTOT + i, ott);  acc8(g_P + 5 * BNTOT + i, ott); acc8(g_P + 8 * BNTOT + i, ott);
    ld8(g_SSp + i, ssS);            acc8(g_SSp + 2 * BNTOT + i, ssS); acc8(g_SSp + 4 * BNTOT + i, ssS);
    ld8(g_SSp + BNTOT + i, ssC);    acc8(g_SSp + 3 * BNTOT + i, ssC); acc8(g_SSp + 5 * BNTOT + i, ssC);
    ld8bf2(g_SCh + i,         g_SCl + i,         sv);
    ld8bf2(g_SCh + BNTOT + i, g_SCl + BNTOT + i, cv);
    ld8(p + i, pv);
    ld8(lm + col, lmv);
    ld8(ld + col, ldv);
    float r1[8], r2[8];
#pragma unroll
    for (int q = 0; q < 8; q++) {
        float conn = sv[q] * ssC[q] - cv[q] * ssS[q];
        r1[q] = ot[q];
        r2[q] = lmv[q] * ott[q] + ldv[q] * ot[q] + conn - pv[q];
    }
    st8f(out + BNTOT + i, r1);
    st8f(out + 2 * BNTOT + i, r2);
}

// ---------------------------------------------------------------------------
// Launch
// ---------------------------------------------------------------------------
extern "C" void kernel_launch(void* const* d_in, const int* in_sizes, int n_in,
                              void* d_out, int out_size)
{
    const float* t    = (const float*)d_in[0];
    const float* p    = (const float*)d_in[1];
    const float* W0   = (const float*)d_in[2];
    const float* b0   = (const float*)d_in[3];
    const float* W1   = (const float*)d_in[4];
    const float* b1   = (const float*)d_in[5];
    const float* W2   = (const float*)d_in[6];
    const float* b2   = (const float*)d_in[7];
    const float* Wout = (const float*)d_in[8];
    const float* bout = (const float*)d_in[9];
    const float* lm   = (const float*)d_in[10];
    const float* ld   = (const float*)d_in[11];
    const float* lb   = (const float*)d_in[12];
    const float* pl   = (const float*)d_in[13];
    const float* pu   = (const float*)d_in[14];
    float* out = (float*)d_out;

    cudaFuncSetAttribute(hmma_gemm_z, cudaFuncAttributeMaxDynamicSharedMemorySize, 3 * STG_BYTES);
    const int GSM = 3 * STG_BYTES;

    __nv_bfloat16 *pXh,*pXl,*pW0h,*pW0l,*pW1h,*pW1l,*pW2h,*pW2l,*pWoh,*pWol,*pLbh,*pLbl;
    __nv_bfloat16 *pAh,*pAl,*pBh,*pBl,*pSCh,*pSCl;
    float *pP,*pSSp;
    cudaGetSymbolAddress((void**)&pXh, g_Xh);   cudaGetSymbolAddress((void**)&pXl, g_Xl);
    cudaGetSymbolAddress((void**)&pW0h, g_W0Th);cudaGetSymbolAddress((void**)&pW0l, g_W0Tl);
    cudaGetSymbolAddress((void**)&pW1h, g_W1Th);cudaGetSymbolAddress((void**)&pW1l, g_W1Tl);
    cudaGetSymbolAddress((void**)&pW2h, g_W2Th);cudaGetSymbolAddress((void**)&pW2l, g_W2Tl);
    cudaGetSymbolAddress((void**)&pWoh, g_WoTh);cudaGetSymbolAddress((void**)&pWol, g_WoTl);
    cudaGetSymbolAddress((void**)&pLbh, g_Lbh); cudaGetSymbolAddress((void**)&pLbl, g_Lbl);
    cudaGetSymbolAddress((void**)&pAh, g_Ah);   cudaGetSymbolAddress((void**)&pAl, g_Al);
    cudaGetSymbolAddress((void**)&pBh, g_Bh);   cudaGetSymbolAddress((void**)&pBl, g_Bl);
    cudaGetSymbolAddress((void**)&pSCh, g_SCh); cudaGetSymbolAddress((void**)&pSCl, g_SCl);
    cudaGetSymbolAddress((void**)&pP, g_P);     cudaGetSymbolAddress((void**)&pSSp, g_SSp);

    const int EW = 256;
    const int VG = BNTOT / (EW * 8);   // 256 blocks for 8-wide kernels

    // prep
    build_x_kernel<<<(BATCH * KP + EW - 1) / EW, EW>>>(t, p, pl, pu);
    prep_all<<<dim3(KP / 32, HD / 32, 5), dim3(32, 8)>>>(W0, W1, W2, Wout, lb);

    // layer 0: [1024,576] x [512,576]^T + b0  (3 segment partials)
    hmma_gemm_z<<<dim3(HD / 128, BATCH / 128, 3), 256, GSM>>>(pXh, pXl, pW0h, pW0l, pP, BATCH, HD, KP, b0, BATCH);
    act0_kernel<<<VG, EW>>>(W0);

    // layer 1: [3072,512] x W1^T
    hmma_gemm_z<<<dim3(HD / 128, 3 * BATCH / 128, 3), 256, GSM>>>(pAh, pAl, pW1h, pW1l, pP, 3 * BATCH, HD, HD, b1, BATCH);
    act12_kernel<<<VG, EW>>>(pBh, pBl);

    // layer 2
    hmma_gemm_z<<<dim3(HD / 128, 3 * BATCH / 128, 3), 256, GSM>>>(pBh, pBl, pW2h, pW2l, pP, 3 * BATCH, HD, HD, b2, BATCH);
    act12_kernel<<<VG, EW>>>(pAh, pAl);

    // output layer -> partials in g_P
    hmma_gemm_z<<<dim3(NB / 128, 3 * BATCH / 128, 3), 256, GSM>>>(pAh, pAl, pWoh, pWol, pP, 3 * BATCH, NB, HD, bout, BATCH);

    // combine value stream -> d_out stream0, sin/cos split
    sincos_kernel<<<VG, EW>>>(out);

    // connectivity: [sin;cos] [2048,512] x lambda_b^T -> partials in g_SSp
    hmma_gemm_z<<<dim3(NB / 128, 2 * BATCH / 128, 3), 256, GSM>>>(pSCh, pSCl, pLbh, pLbl, pSSp, 2 * BATCH, NB, NB, nullptr, 0);

    // combine streams 1,2 + physics -> d_out
    final_kernel<<<VG, EW>>>(out, lm, ld, p);
}

// round 10
// speedup vs baseline: 2.8568x; 1.1916x over previous
#include <cuda_runtime.h>
#include <cuda_fp16.h>
#include <math.h>
#include <stdint.h>

// Problem dims
#define BATCH 1024
#define NB    512
#define HD    512
#define KP    576            // padded input dim (1+512 -> 576 = 9*64)
#define BNTOT (BATCH*NB)     // 524288

// ---------------------------------------------------------------------------
// Scratch (device globals)
// ---------------------------------------------------------------------------
__device__ __half g_Xh[BATCH*KP],  g_Xl[BATCH*KP];
__device__ __half g_W0T[HD*KP];      // W0^T padded [512 x 576], single fp16
__device__ __half g_W1T[HD*HD];
__device__ __half g_W2T[HD*HD];
__device__ __half g_WoT[HD*NB];      // Wout^T [512 x 512]
__device__ __half g_Lb [NB*NB];      // lambda_b rows
__device__ __half g_Ah[3*BNTOT],   g_Al[3*BNTOT];    // activations ping (hi/lo fp16)
__device__ __half g_Bh[3*BNTOT],   g_Bl[3*BNTOT];    // activations pong
__device__ __half g_SCh[2*BNTOT],  g_SCl[2*BNTOT];   // [sin ; cos] hi/lo
__device__ float g_P  [2*3*BNTOT];   // GEMM partials: segment s at offset s*M*N
__device__ float g_SSp[2*2*BNTOT];   // conn GEMM partials

__device__ __forceinline__ void split2h(float x, __half* h, __half* l) {
    __half hi = __float2half_rn(x);
    *h = hi;
    *l = __float2half_rn(x - __half2float(hi));
}

__device__ __forceinline__ uint32_t smem_u32(const void* p) {
    uint32_t a;
    asm("{ .reg .u64 t; cvta.to.shared.u64 t, %1; cvt.u32.u64 %0, t; }" : "=r"(a) : "l"(p));
    return a;
}

__device__ __forceinline__ void mma_f16(float* d, const uint32_t* a, uint32_t b0, uint32_t b1) {
    asm volatile(
        "mma.sync.aligned.m16n8k16.row.col.f32.f16.f16.f32 "
        "{%0,%1,%2,%3},{%4,%5,%6,%7},{%8,%9},{%0,%1,%2,%3};"
        : "+f"(d[0]), "+f"(d[1]), "+f"(d[2]), "+f"(d[3])
        : "r"(a[0]), "r"(a[1]), "r"(a[2]), "r"(a[3]), "r"(b0), "r"(b1));
}

// 1-MUFU tanh (validated R9): e=exp(-2|u|), FFMA-only reciprocal of 1+e in (1,2]
__device__ __forceinline__ float tanh_fast(float u) {
    float au = fabsf(u);
    float e = __expf(-2.f * au);
    float d = 1.f + e;
    float r = __fmaf_rn(-0.47058824f, d, 1.41176471f);  // 24/17 - 8/17*d
    r = r * (2.f - d * r);
    r = r * (2.f - d * r);
    r = r * (2.f - d * r);
    float t = (1.f - e) * r;
    return copysignf(t, u);
}

// ---- 8-wide vector helpers --------------------------------------------------
__device__ __forceinline__ void ld8(const float* p, float r[8]) {
    float4 a = *(const float4*)p, b = *(const float4*)(p + 4);
    r[0]=a.x; r[1]=a.y; r[2]=a.z; r[3]=a.w; r[4]=b.x; r[5]=b.y; r[6]=b.z; r[7]=b.w;
}
__device__ __forceinline__ void acc8(const float* p, float r[8]) {
    float4 a = *(const float4*)p, b = *(const float4*)(p + 4);
    r[0]+=a.x; r[1]+=a.y; r[2]+=a.z; r[3]+=a.w; r[4]+=b.x; r[5]+=b.y; r[6]+=b.z; r[7]+=b.w;
}
__device__ __forceinline__ void st8f(float* p, const float r[8]) {
    *(float4*)p       = make_float4(r[0], r[1], r[2], r[3]);
    *(float4*)(p + 4) = make_float4(r[4], r[5], r[6], r[7]);
}
// split 8 fp32 -> hi/lo fp16 arrays (two uint4 stores)
__device__ __forceinline__ void split8h(const float r[8], __half* ph, __half* pl) {
    uint32_t h[4], l[4];
#pragma unroll
    for (int q = 0; q < 4; q++) {
        float x0 = r[2*q], x1 = r[2*q+1];
        __half2 hh = __floats2half2_rn(x0, x1);
        float f0 = __half2float(__low2half(hh)), f1 = __half2float(__high2half(hh));
        __half2 ll = __floats2half2_rn(x0 - f0, x1 - f1);
        h[q] = *(uint32_t*)&hh;
        l[q] = *(uint32_t*)&ll;
    }
    *(uint4*)ph = make_uint4(h[0], h[1], h[2], h[3]);
    *(uint4*)pl = make_uint4(l[0], l[1], l[2], l[3]);
}
// read 8 (hi,lo) fp16 pairs -> fp32 sum
__device__ __forceinline__ void ld8h2(const __half* ph, const __half* pl, float r[8]) {
    uint4 h = *(const uint4*)ph, l = *(const uint4*)pl;
    uint32_t hv[4] = {h.x, h.y, h.z, h.w};
    uint32_t lv[4] = {l.x, l.y, l.z, l.w};
#pragma unroll
    for (int q = 0; q < 4; q++) {
        __half2 hb = *(__half2*)&hv[q];
        __half2 lb = *(__half2*)&lv[q];
        r[2*q]   = __half2float(__low2half(hb))  + __half2float(__low2half(lb));
        r[2*q+1] = __half2float(__high2half(hb)) + __half2float(__high2half(lb));
    }
}

// ---------------------------------------------------------------------------
// HMMA 2-segment fp16 GEMM: C = (Ah + Al) * B^T, B single fp16 [N,K] row-major.
// blockIdx.z = s in {0,1}: s=0: Ah*B (+bias), s=1: Al*B.
// CTA tile 128(M) x 64(N), Kc=64 (128B rows, XOR-8 swizzle), 3-stage cp.async.
// 8 warps: wm=wid&3 (4x32 M), wn=wid>>2 (2x32 N). Warp tile 32x32.
// smem/stage: A 16KB + B 8KB = 24KB; 3 stages = 72KB; 2 CTAs/SM.
// ---------------------------------------------------------------------------
#define STG_BYTES 24576
#define B_OFF     16384

__global__ void __launch_bounds__(256, 2)
hmma_gemm_z(const __half* __restrict__ Ah, const __half* __restrict__ Al,
            const __half* __restrict__ B,
            float* __restrict__ Cpart, int M, int N, int K,
            const float* __restrict__ bias, int bias_rows)
{
    extern __shared__ __align__(1024) char smem[];
    const uint32_t sb = smem_u32(smem);
    const int tid = threadIdx.x;
    const int lane = tid & 31;
    const int wid = tid >> 5;
    const int wm = wid & 3;          // M direction (4 x 32 = 128)
    const int wn = wid >> 2;         // N direction (2 x 32 = 64)
    const int m0 = blockIdx.y * 128;
    const int n0 = blockIdx.x * 64;
    const int s  = blockIdx.z;
    const int ncK = K >> 6;

    const __half* __restrict__ Ap = (s == 0) ? Ah : Al;
    float* __restrict__ C = Cpart + (size_t)s * M * N;
    const float* bp = (s == 0) ? bias : nullptr;

    float acc[2][4][4];
#pragma unroll
    for (int i = 0; i < 2; i++)
#pragma unroll
        for (int j = 0; j < 4; j++)
#pragma unroll
            for (int q = 0; q < 4; q++) acc[i][j][q] = 0.f;

    auto load_stage = [&](int kk, int stg) {
        const int kbase = kk << 6;
        const uint32_t abase = sb + stg * STG_BYTES;
        const uint32_t bbase = abase + B_OFF;
#pragma unroll
        for (int pass = 0; pass < 4; pass++) {       // A: 128 rows x 128B
            int idx = pass * 256 + tid;
            int row = idx >> 3, ch = idx & 7;
            uint32_t sa = abase + row * 128 + ((ch ^ (row & 7)) << 4);
            const void* ga = Ap + (size_t)(m0 + row) * K + kbase + ch * 8;
            asm volatile("cp.async.cg.shared.global [%0], [%1], 16;" :: "r"(sa), "l"(ga));
        }
#pragma unroll
        for (int pass = 0; pass < 2; pass++) {       // B: 64 rows x 128B
            int idx = pass * 256 + tid;
            int row = idx >> 3, ch = idx & 7;
            uint32_t sa = bbase + row * 128 + ((ch ^ (row & 7)) << 4);
            const void* ga = B + (size_t)(n0 + row) * K + kbase + ch * 8;
            asm volatile("cp.async.cg.shared.global [%0], [%1], 16;" :: "r"(sa), "l"(ga));
        }
    };

    load_stage(0, 0);
    asm volatile("cp.async.commit_group;" ::: "memory");
    load_stage(1, 1);
    asm volatile("cp.async.commit_group;" ::: "memory");

    int cbuf = 0, nbuf = 2;
    for (int c = 0; c < ncK; c++) {
        asm volatile("cp.async.wait_group 1;" ::: "memory");
        __syncthreads();
        if (c + 2 < ncK) load_stage(c + 2, nbuf);
        asm volatile("cp.async.commit_group;" ::: "memory");

        const uint32_t abase = sb + cbuf * STG_BYTES;
        const uint32_t bbase = abase + B_OFF;

#pragma unroll
        for (int kb = 0; kb < 4; kb++) {
            uint32_t a[2][4];
#pragma unroll
            for (int i = 0; i < 2; i++) {
                int row = wm * 32 + i * 16 + (lane & 15);
                int ch  = kb * 2 + (lane >> 4);
                uint32_t ad = abase + row * 128 + ((ch ^ (row & 7)) << 4);
                asm volatile("ldmatrix.sync.aligned.m8n8.x4.shared.b16 {%0,%1,%2,%3}, [%4];"
                             : "=r"(a[i][0]), "=r"(a[i][1]), "=r"(a[i][2]), "=r"(a[i][3])
                             : "r"(ad));
            }
#pragma unroll
            for (int j16 = 0; j16 < 2; j16++) {
                uint32_t b[4];
                int rn  = (lane & 7) + ((lane >> 4) << 3);
                int row = wn * 32 + j16 * 16 + rn;
                int ch  = kb * 2 + ((lane >> 3) & 1);
                uint32_t bd = bbase + row * 128 + ((ch ^ (row & 7)) << 4);
                asm volatile("ldmatrix.sync.aligned.m8n8.x4.shared.b16 {%0,%1,%2,%3}, [%4];"
                             : "=r"(b[0]), "=r"(b[1]), "=r"(b[2]), "=r"(b[3])
                             : "r"(bd));
#pragma unroll
                for (int i = 0; i < 2; i++) {
                    mma_f16(acc[i][2 * j16],     a[i], b[0], b[1]);
                    mma_f16(acc[i][2 * j16 + 1], a[i], b[2], b[3]);
                }
            }
        }
        cbuf = (cbuf == 2) ? 0 : cbuf + 1;
        nbuf = (nbuf == 2) ? 0 : nbuf + 1;
    }

    // epilogue
    const int gr  = lane >> 2;
    const int cp2 = (lane & 3) * 2;
#pragma unroll
    for (int i = 0; i < 2; i++) {
#pragma unroll
        for (int j8 = 0; j8 < 4; j8++) {
            int col = n0 + wn * 32 + j8 * 8 + cp2;
            int r0  = m0 + wm * 32 + i * 16 + gr;
            float bx = 0.f, by = 0.f;
            if (bp) { bx = bp[col]; by = bp[col + 1]; }
#pragma unroll
            for (int rr = 0; rr < 2; rr++) {
                int row = r0 + rr * 8;
                float2 v;
                v.x = acc[i][j8][2 * rr + 0];
                v.y = acc[i][j8][2 * rr + 1];
                if (bp && row < bias_rows) { v.x += bx; v.y += by; }
                *reinterpret_cast<float2*>(&C[(size_t)row * N + col]) = v;
            }
        }
    }
}

// ---------------------------------------------------------------------------
// Fused prep: z<4 -> tiled transpose + fp16 convert of W0/W1/W2/Wout;
// z==4 -> lambda_b straight fp16 convert. grid (18, 16, 5), block (32, 8).
// ---------------------------------------------------------------------------
__global__ void prep_all(const float* __restrict__ W0, const float* __restrict__ W1,
                         const float* __restrict__ W2, const float* __restrict__ Wo,
                         const float* __restrict__ lb)
{
    const int tx = threadIdx.x, ty = threadIdx.y;
    const int kb = blockIdx.x * 32, nb = blockIdx.y * 32;
    const int z = blockIdx.z;

    if (z == 4) {
        if (kb >= NB) return;
#pragma unroll
        for (int i = 0; i < 32; i += 8) {
            size_t o = (size_t)(nb + ty + i) * NB + kb + tx;
            g_Lb[o] = __float2half_rn(lb[o]);
        }
        return;
    }

    const float* W; __half* oh; int Kin, Kout;
    if (z == 0)      { W = W0; oh = g_W0T; Kin = NB + 1; Kout = KP; }
    else if (z == 1) { W = W1; oh = g_W1T; Kin = HD;     Kout = HD; }
    else if (z == 2) { W = W2; oh = g_W2T; Kin = HD;     Kout = HD; }
    else             { W = Wo; oh = g_WoT; Kin = HD;     Kout = HD; }
    if (kb >= Kout) return;

    __shared__ float tile[32][33];
#pragma unroll
    for (int i = 0; i < 32; i += 8) {
        int k = kb + ty + i;
        tile[ty + i][tx] = (k < Kin) ? W[(size_t)k * HD + nb + tx] : 0.f;
    }
    __syncthreads();
#pragma unroll
    for (int i = 0; i < 32; i += 8) {
        int n = nb + ty + i;
        size_t o = (size_t)n * Kout + kb + tx;
        oh[o] = __float2half_rn(tile[tx][ty + i]);
    }
}

// ---------------------------------------------------------------------------
// Elementwise kernels
// ---------------------------------------------------------------------------
__global__ void build_x_kernel(const float* __restrict__ t, const float* __restrict__ p,
                               const float* __restrict__ pl, const float* __restrict__ pu)
{
    int idx = blockIdx.x * blockDim.x + threadIdx.x;
    if (idx >= BATCH * KP) return;
    int row = idx / KP, col = idx - row * KP;
    float v;
    if (col == 0) v = 0.2f * t[row] - 1.0f;
    else if (col <= NB) {
        int j = col - 1;
        float lo = pl[j], hi = pu[j];
        v = (hi == lo) ? 0.f : (__fdividef(2.f * (p[row * NB + j] - lo), hi - lo) - 1.f);
    } else v = 0.f;
    split2h(v, &g_Xh[idx], &g_Xl[idx]);
}

// layer0: 2 partials at {0,1}*BNTOT (segment stride = M*N = BNTOT)
__global__ void act0_kernel(const float* __restrict__ W0)
{
    int i = (blockIdx.x * blockDim.x + threadIdx.x) * 8;
    if (i >= BNTOT) return;
    int col = i & (HD - 1);
    float u[8], w0[8];
    ld8(g_P + i, u); acc8(g_P + BNTOT + i, u);
    ld8(W0 + col, w0);                           // W0 row 0
    float a[8], d1[8], d2[8];
#pragma unroll
    for (int q = 0; q < 8; q++) {
        float av = tanh_fast(u[q]);
        float ssq = 1.f - av * av;
        float gth = 0.2f * w0[q];
        a[q]  = av;
        d1[q] = ssq * gth;
        d2[q] = -2.f * av * ssq * gth * gth;
    }
    split8h(a,  g_Ah + i,             g_Al + i);
    split8h(d1, g_Ah + BNTOT + i,     g_Al + BNTOT + i);
    split8h(d2, g_Ah + 2 * BNTOT + i, g_Al + 2 * BNTOT + i);
}

// layers 1/2: segment stride = 3*BNTOT; stream t at t*BNTOT within segment
__global__ void act12_kernel(__half* __restrict__ oh, __half* __restrict__ ol)
{
    int i = (blockIdx.x * blockDim.x + threadIdx.x) * 8;
    if (i >= BNTOT) return;
    float u[8], v[8], w[8];
    ld8(g_P + i, u);              acc8(g_P + 3 * BNTOT + i, u);
    ld8(g_P + BNTOT + i, v);      acc8(g_P + 4 * BNTOT + i, v);
    ld8(g_P + 2 * BNTOT + i, w);  acc8(g_P + 5 * BNTOT + i, w);
    float a[8], d1[8], d2[8];
#pragma unroll
    for (int q = 0; q < 8; q++) {
        float av = tanh_fast(u[q]);
        float ssq = 1.f - av * av;
        a[q]  = av;
        d1[q] = ssq * v[q];
        d2[q] = ssq * (w[q] - 2.f * av * v[q] * v[q]);
    }
    split8h(a,  oh + i,             ol + i);
    split8h(d1, oh + BNTOT + i,     ol + BNTOT + i);
    split8h(d2, oh + 2 * BNTOT + i, ol + 2 * BNTOT + i);
}

// combine out value stream -> d_out stream 0, emit sin/cos hi/lo
__global__ void sincos_kernel(float* __restrict__ out)
{
    int i = (blockIdx.x * blockDim.x + threadIdx.x) * 8;
    if (i >= BNTOT) return;
    float o[8];
    ld8(g_P + i, o); acc8(g_P + 3 * BNTOT + i, o);
    st8f(out + i, o);
    float sv[8], cv[8];
#pragma unroll
    for (int q = 0; q < 8; q++) __sincosf(o[q], &sv[q], &cv[q]);
    split8h(sv, g_SCh + i,         g_SCl + i);
    split8h(cv, g_SCh + BNTOT + i, g_SCl + BNTOT + i);
}

// combine streams 1,2 + conn partials + physics -> d_out (no MUFU)
__global__ void final_kernel(float* __restrict__ out, const float* __restrict__ lm,
                             const float* __restrict__ ld, const float* __restrict__ p)
{
    int i = (blockIdx.x * blockDim.x + threadIdx.x) * 8;
    if (i >= BNTOT) return;
    int col = i & (NB - 1);
    float ot[8], ott[8], ssS[8], ssC[8], pv[8], lmv[8], ldv[8], sv[8], cv[8];
    ld8(g_P + BNTOT + i, ot);       acc8(g_P + 4 * BNTOT + i, ot);
    ld8(g_P + 2 * BNTOT + i, ott);  acc8(g_P + 5 * BNTOT + i, ott);
    ld8(g_SSp + i, ssS);            acc8(g_SSp + 2 * BNTOT + i, ssS);
    ld8(g_SSp + BNTOT + i, ssC);    acc8(g_SSp + 3 * BNTOT + i, ssC);
    ld8h2(g_SCh + i,         g_SCl + i,         sv);
    ld8h2(g_SCh + BNTOT + i, g_SCl + BNTOT + i, cv);
    ld8(p + i, pv);
    ld8(lm + col, lmv);
    ld8(ld + col, ldv);
    float r1[8], r2[8];
#pragma unroll
    for (int q = 0; q < 8; q++) {
        float conn = sv[q] * ssC[q] - cv[q] * ssS[q];
        r1[q] = ot[q];
        r2[q] = lmv[q] * ott[q] + ldv[q] * ot[q] + conn - pv[q];
    }
    st8f(out + BNTOT + i, r1);
    st8f(out + 2 * BNTOT + i, r2);
}

// ---------------------------------------------------------------------------
// Launch
// ---------------------------------------------------------------------------
extern "C" void kernel_launch(void* const* d_in, const int* in_sizes, int n_in,
                              void* d_out, int out_size)
{
    const float* t    = (const float*)d_in[0];
    const float* p    = (const float*)d_in[1];
    const float* W0   = (const float*)d_in[2];
    const float* b0   = (const float*)d_in[3];
    const float* W1   = (const float*)d_in[4];
    const float* b1   = (const float*)d_in[5];
    const float* W2   = (const float*)d_in[6];
    const float* b2   = (const float*)d_in[7];
    const float* Wout = (const float*)d_in[8];
    const float* bout = (const float*)d_in[9];
    const float* lm   = (const float*)d_in[10];
    const float* ld   = (const float*)d_in[11];
    const float* lb   = (const float*)d_in[12];
    const float* pl   = (const float*)d_in[13];
    const float* pu   = (const float*)d_in[14];
    float* out = (float*)d_out;

    cudaFuncSetAttribute(hmma_gemm_z, cudaFuncAttributeMaxDynamicSharedMemorySize, 3 * STG_BYTES);
    const int GSM = 3 * STG_BYTES;

    __half *pXh,*pXl,*pW0,*pW1,*pW2,*pWo,*pLb,*pAh,*pAl,*pBh,*pBl,*pSCh,*pSCl;
    float *pP,*pSSp;
    cudaGetSymbolAddress((void**)&pXh, g_Xh);   cudaGetSymbolAddress((void**)&pXl, g_Xl);
    cudaGetSymbolAddress((void**)&pW0, g_W0T);
    cudaGetSymbolAddress((void**)&pW1, g_W1T);
    cudaGetSymbolAddress((void**)&pW2, g_W2T);
    cudaGetSymbolAddress((void**)&pWo, g_WoT);
    cudaGetSymbolAddress((void**)&pLb, g_Lb);
    cudaGetSymbolAddress((void**)&pAh, g_Ah);   cudaGetSymbolAddress((void**)&pAl, g_Al);
    cudaGetSymbolAddress((void**)&pBh, g_Bh);   cudaGetSymbolAddress((void**)&pBl, g_Bl);
    cudaGetSymbolAddress((void**)&pSCh, g_SCh); cudaGetSymbolAddress((void**)&pSCl, g_SCl);
    cudaGetSymbolAddress((void**)&pP, g_P);     cudaGetSymbolAddress((void**)&pSSp, g_SSp);

    const int EW = 256;
    const int VG = BNTOT / (EW * 8);

    // prep
    build_x_kernel<<<(BATCH * KP + EW - 1) / EW, EW>>>(t, p, pl, pu);
    prep_all<<<dim3(KP / 32, HD / 32, 5), dim3(32, 8)>>>(W0, W1, W2, Wout, lb);

    // layer 0: [1024,576] x [512,576]^T + b0  (2 segment partials)
    hmma_gemm_z<<<dim3(HD / 64, BATCH / 128, 2), 256, GSM>>>(pXh, pXl, pW0, pP, BATCH, HD, KP, b0, BATCH);
    act0_kernel<<<VG, EW>>>(W0);

    // layer 1: [3072,512] x W1^T
    hmma_gemm_z<<<dim3(HD / 64, 3 * BATCH / 128, 2), 256, GSM>>>(pAh, pAl, pW1, pP, 3 * BATCH, HD, HD, b1, BATCH);
    act12_kernel<<<VG, EW>>>(pBh, pBl);

    // layer 2
    hmma_gemm_z<<<dim3(HD / 64, 3 * BATCH / 128, 2), 256, GSM>>>(pBh, pBl, pW2, pP, 3 * BATCH, HD, HD, b2, BATCH);
    act12_kernel<<<VG, EW>>>(pAh, pAl);

    // output layer -> partials in g_P
    hmma_gemm_z<<<dim3(NB / 64, 3 * BATCH / 128, 2), 256, GSM>>>(pAh, pAl, pWo, pP, 3 * BATCH, NB, HD, bout, BATCH);

    // combine value stream -> d_out stream0, sin/cos split
    sincos_kernel<<<VG, EW>>>(out);

    // connectivity: [sin;cos] [2048,512] x lambda_b^T -> partials in g_SSp
    hmma_gemm_z<<<dim3(NB / 64, 2 * BATCH / 128, 2), 256, GSM>>>(pSCh, pSCl, pLb, pSSp, 2 * BATCH, NB, NB, nullptr, 0);

    // combine streams 1,2 + physics -> d_out
    final_kernel<<<VG, EW>>>(out, lm, ld, p);
}